// round 5
// baseline (speedup 1.0000x reference)
#include <cuda_runtime.h>
#include <math.h>
#include <stdint.h>

// Problem dims
#define BATCH 64
#define SEQLEN 256
#define DMODEL 256
#define DINNER 512
#define DSTATE 16
#define DTRANK 16
#define DCONV 4
#define DIMIN 256
#define DIMOUT 64
#define BL (BATCH * SEQLEN)      // 16384
#define SEG 8
#define LSEG (SEQLEN / SEG)      // 32

// Scratch (device globals: no cudaMalloc allowed)
__device__ float g_xin[BL * DINNER];
__device__ float g_z[BL * DINNER];
__device__ float g_xc[BL * DINNER];
__device__ float g_delta[BL * DINNER];
__device__ float g_Bm[BL * DSTATE];
__device__ float g_Cm[BL * DSTATE];
__device__ float g_ybar[BATCH * DINNER];

// ---------------------------------------------------------------------------
// K1: xz = input @ W_in^T ; split into x_in and z   (R2-proven SGEMM)
// M=16384, N=1024, K=256. BM=BN=128, BK=16, 256 threads, 8x8 micro-tile.
// ---------------------------------------------------------------------------
__global__ __launch_bounds__(256) void k1_gemm(const float* __restrict__ X,
                                               const float* __restrict__ W) {
    __shared__ float As[16][132];   // k-major, padded
    __shared__ float Bs[16][132];

    const int m0 = blockIdx.y * 128;
    const int n0 = blockIdx.x * 128;
    const int tid = threadIdx.x;
    const int tx = tid & 15;
    const int ty = tid >> 4;

    float acc[8][8];
#pragma unroll
    for (int i = 0; i < 8; i++)
#pragma unroll
        for (int j = 0; j < 8; j++) acc[i][j] = 0.f;

    for (int k0 = 0; k0 < 256; k0 += 16) {
#pragma unroll
        for (int i = 0; i < 2; i++) {
            int f = tid + i * 256;          // float4 index 0..511
            int m = f >> 2;                 // 0..127
            int k4 = (f & 3) * 4;           // 0,4,8,12
            float4 va = *reinterpret_cast<const float4*>(&X[(m0 + m) * 256 + k0 + k4]);
            As[k4 + 0][m] = va.x; As[k4 + 1][m] = va.y;
            As[k4 + 2][m] = va.z; As[k4 + 3][m] = va.w;
            float4 vb = *reinterpret_cast<const float4*>(&W[(n0 + m) * 256 + k0 + k4]);
            Bs[k4 + 0][m] = vb.x; Bs[k4 + 1][m] = vb.y;
            Bs[k4 + 2][m] = vb.z; Bs[k4 + 3][m] = vb.w;
        }
        __syncthreads();

#pragma unroll
        for (int kk = 0; kk < 16; kk++) {
            float a[8], b[8];
            *reinterpret_cast<float4*>(&a[0]) = *reinterpret_cast<const float4*>(&As[kk][ty * 8]);
            *reinterpret_cast<float4*>(&a[4]) = *reinterpret_cast<const float4*>(&As[kk][ty * 8 + 4]);
            *reinterpret_cast<float4*>(&b[0]) = *reinterpret_cast<const float4*>(&Bs[kk][tx * 8]);
            *reinterpret_cast<float4*>(&b[4]) = *reinterpret_cast<const float4*>(&Bs[kk][tx * 8 + 4]);
#pragma unroll
            for (int i = 0; i < 8; i++)
#pragma unroll
                for (int j = 0; j < 8; j++) acc[i][j] = fmaf(a[i], b[j], acc[i][j]);
        }
        __syncthreads();
    }

    float* dstbase = (n0 < DINNER) ? g_xin : g_z;
    const int ncol = (n0 < DINNER) ? (n0 + tx * 8) : (n0 - DINNER + tx * 8);
#pragma unroll
    for (int i = 0; i < 8; i++) {
        int m = m0 + ty * 8 + i;
        float4 o0 = make_float4(acc[i][0], acc[i][1], acc[i][2], acc[i][3]);
        float4 o1 = make_float4(acc[i][4], acc[i][5], acc[i][6], acc[i][7]);
        *reinterpret_cast<float4*>(&dstbase[m * DINNER + ncol]) = o0;
        *reinterpret_cast<float4*>(&dstbase[m * DINNER + ncol + 4]) = o1;
    }
}

// ---------------------------------------------------------------------------
// K3 (fused conv + proj): conv(width4,causal)+bias+SiLU in smem, write g_xc,
// then x_dbl = xc @ W_xproj^T (48 out); split dt/B/C;
// delta = softplus(dt @ W_dt^T + b_dt).
// 16 (b,l) rows per block + 3 halo rows, 512 threads (one per channel).
// ---------------------------------------------------------------------------
#define K3ROWS 16
__global__ __launch_bounds__(512) void k3_convproj(const float* __restrict__ cw,
                                                   const float* __restrict__ cb,
                                                   const float* __restrict__ Wx,
                                                   const float* __restrict__ Wdt,
                                                   const float* __restrict__ bdt) {
    const int bl0 = blockIdx.x * K3ROWS;
    const int l0 = bl0 & (SEQLEN - 1);          // 0..240, block never crosses batch
    __shared__ float sxin[K3ROWS + 3][DINNER];  // rows: bl0-3 .. bl0+15
    __shared__ float sdbl[K3ROWS][48];
    const int tid = threadIdx.x;

    // load x_in rows (zero-fill out-of-batch halo)
#pragma unroll
    for (int j = 0; j < K3ROWS + 3; j++) {
        int bl = bl0 - 3 + j;
        sxin[j][tid] = (l0 + j >= 3) ? g_xin[(size_t)bl * DINNER + tid] : 0.f;
    }

    // conv + bias + SiLU, in place (thread-private column, read-before-write)
    const float w0 = cw[tid * 4 + 0], w1 = cw[tid * 4 + 1];
    const float w2 = cw[tid * 4 + 2], w3 = cw[tid * 4 + 3];
    const float bias = cb[tid];
#pragma unroll
    for (int r = 0; r < K3ROWS; r++) {
        float sum = bias;
        sum = fmaf(sxin[r + 0][tid], w0, sum);
        sum = fmaf(sxin[r + 1][tid], w1, sum);
        sum = fmaf(sxin[r + 2][tid], w2, sum);
        sum = fmaf(sxin[r + 3][tid], w3, sum);
        float xc = sum / (1.f + expf(-sum));
        sxin[r][tid] = xc;                       // xc row r now at slot r
        g_xc[(size_t)(bl0 + r) * DINNER + tid] = xc;
    }
    __syncthreads();

    const int w = tid >> 5, lane = tid & 31;
#pragma unroll
    for (int oi = 0; oi < 3; oi++) {
        const int o = w + oi * 16;
        float s[K3ROWS];
#pragma unroll
        for (int r = 0; r < K3ROWS; r++) s[r] = 0.f;
#pragma unroll
        for (int it = 0; it < DINNER / 128; it++) {
            const int k = it * 128 + lane * 4;
            float4 wv = *reinterpret_cast<const float4*>(&Wx[o * DINNER + k]);
#pragma unroll
            for (int r = 0; r < K3ROWS; r++) {
                s[r] = fmaf(sxin[r][k + 0], wv.x, s[r]);
                s[r] = fmaf(sxin[r][k + 1], wv.y, s[r]);
                s[r] = fmaf(sxin[r][k + 2], wv.z, s[r]);
                s[r] = fmaf(sxin[r][k + 3], wv.w, s[r]);
            }
        }
#pragma unroll
        for (int off = 16; off; off >>= 1)
#pragma unroll
            for (int r = 0; r < K3ROWS; r++) s[r] += __shfl_down_sync(0xFFFFFFFFu, s[r], off);
        if (lane == 0) {
#pragma unroll
            for (int r = 0; r < K3ROWS; r++) sdbl[r][o] = s[r];
        }
    }
    __syncthreads();

    if (tid < K3ROWS * 16) {
        int r = tid >> 4, n = tid & 15;
        g_Bm[(size_t)(bl0 + r) * DSTATE + n] = sdbl[r][DTRANK + n];
        g_Cm[(size_t)(bl0 + r) * DSTATE + n] = sdbl[r][DTRANK + DSTATE + n];
    }

    float bv = bdt[tid];
    float wr[DTRANK];
#pragma unroll
    for (int i = 0; i < DTRANK; i++) wr[i] = Wdt[tid * DTRANK + i];
#pragma unroll
    for (int r = 0; r < K3ROWS; r++) {
        float acc = bv;
#pragma unroll
        for (int i = 0; i < DTRANK; i++) acc = fmaf(sdbl[r][i], wr[i], acc);
        float sp = fmaxf(acc, 0.f) + log1pf(expf(-fabsf(acc)));
        g_delta[(size_t)(bl0 + r) * DINNER + tid] = sp;
    }
}

// ---------------------------------------------------------------------------
// K4: selective scan, fully fused (segment scan + in-block combine).
// Grid (64, 32), 128 threads = 8 segments x 16 channels.
// Partials handed off via smem; g_ybar written directly.
// ---------------------------------------------------------------------------
template <bool FAST>
__device__ __forceinline__ void seg_scan_core(
    int b, int d, int s, const float* __restrict__ A, float Dp,
    float* __restrict__ P, float* __restrict__ V, float* __restrict__ Wc,
    float& cOut)
{
#pragma unroll
    for (int n = 0; n < DSTATE; n++) { P[n] = 1.f; V[n] = 0.f; Wc[n] = 0.f; }
    float c = 0.f;
    const float A0 = A[0];

    const int l0 = s * LSEG;
    const float* pdelta = g_delta + ((size_t)(b * SEQLEN + l0)) * DINNER + d;
    const float* pxc    = g_xc    + ((size_t)(b * SEQLEN + l0)) * DINNER + d;
    const float* pz     = g_z     + ((size_t)(b * SEQLEN + l0)) * DINNER + d;
    const float4* pB4 = reinterpret_cast<const float4*>(g_Bm + ((size_t)(b * SEQLEN + l0)) * DSTATE);
    const float4* pC4 = reinterpret_cast<const float4*>(g_Cm + ((size_t)(b * SEQLEN + l0)) * DSTATE);

    float dt  = pdelta[0];
    float xcv = pxc[0];
    float zv  = pz[0];

#pragma unroll 4
    for (int l = 0; l < LSEG; l++) {
        float dtn = 0.f, xcn = 0.f, zvn = 0.f;
        if (l + 1 < LSEG) {
            dtn = pdelta[(l + 1) * DINNER];
            xcn = pxc[(l + 1) * DINNER];
            zvn = pz[(l + 1) * DINNER];
        }
        float gate = __fdividef(zv, 1.f + __expf(-zv));   // z * sigmoid(z)
        float du = dt * xcv;
        float yl = 0.f;

        float dA[DSTATE];
        if (FAST) {
            float r  = __expf(dt * A0);
            float r2 = r * r;
            float r4 = r2 * r2;
            float r8 = r4 * r4;
            dA[0]  = r;          dA[1]  = r2;         dA[2]  = r2 * r;     dA[3]  = r4;
            dA[4]  = r4 * r;     dA[5]  = r4 * r2;    dA[6]  = r4 * dA[2]; dA[7]  = r8;
            dA[8]  = r8 * r;     dA[9]  = r8 * r2;    dA[10] = r8 * dA[2]; dA[11] = r8 * r4;
            dA[12] = r8 * dA[4]; dA[13] = r8 * dA[5]; dA[14] = r8 * dA[6]; dA[15] = r8 * r8;
        } else {
#pragma unroll
            for (int n = 0; n < DSTATE; n++) dA[n] = __expf(dt * A[n]);
        }

#pragma unroll
        for (int q = 0; q < 4; q++) {
            float4 Bq = __ldg(&pB4[l * 4 + q]);
            float4 Cq = __ldg(&pC4[l * 4 + q]);
            float Bn[4] = {Bq.x, Bq.y, Bq.z, Bq.w};
            float Cn[4] = {Cq.x, Cq.y, Cq.z, Cq.w};
#pragma unroll
            for (int i = 0; i < 4; i++) {
                const int n = q * 4 + i;
                P[n] *= dA[n];
                V[n] = fmaf(dA[n], V[n], du * Bn[i]);
                yl = fmaf(V[n], Cn[i], yl);
                Wc[n] = fmaf(gate * Cn[i], P[n], Wc[n]);
            }
        }
        c = fmaf(gate, fmaf(xcv, Dp, yl), c);
        dt = dtn; xcv = xcn; zv = zvn;
    }
    cOut = c;
}

__global__ __launch_bounds__(128) void k4_scan(const float* __restrict__ A_log,
                                               const float* __restrict__ D_param) {
    const int b = blockIdx.x;
    const int d0 = blockIdx.y * 16;
    const int tid = threadIdx.x;
    const int s = tid >> 4;        // 0..7
    const int dl = tid & 15;       // 0..15
    const int d = d0 + dl;

    __shared__ float sP[SEG][16][17];
    __shared__ float sV[SEG][16][17];
    __shared__ float sW[SEG][16][17];
    __shared__ float sc[SEG][16];

    float A[DSTATE];
    bool fast = true;
#pragma unroll
    for (int n = 0; n < DSTATE; n++) {
        A[n] = -expf(A_log[d * DSTATE + n]);
        fast = fast && (fabsf(A[n] - (float)(n + 1) * A[0]) <= 1e-4f * fabsf(A[n]));
    }
    const float Dp = D_param[d];

    float P[DSTATE], V[DSTATE], Wc[DSTATE], c;
    if (fast) seg_scan_core<true >(b, d, s, A, Dp, P, V, Wc, c);
    else      seg_scan_core<false>(b, d, s, A, Dp, P, V, Wc, c);

#pragma unroll
    for (int n = 0; n < DSTATE; n++) {
        sP[s][dl][n] = P[n];
        sV[s][dl][n] = V[n];
        sW[s][dl][n] = Wc[n];
    }
    sc[s][dl] = c;
    __syncthreads();

    // combine: thread role (dl2 = tid>>3, j = tid&7), n0 = j, n1 = j+8
    const int dl2 = tid >> 3;
    const int j = tid & 7;
    const int n0 = j, n1 = j + 8;

    float h0 = 0.f, h1 = 0.f, ys = 0.f;
#pragma unroll
    for (int ss = 0; ss < SEG; ss++) {
        ys = fmaf(sW[ss][dl2][n0], h0, ys);
        ys = fmaf(sW[ss][dl2][n1], h1, ys);
        h0 = fmaf(sP[ss][dl2][n0], h0, sV[ss][dl2][n0]);
        h1 = fmaf(sP[ss][dl2][n1], h1, sV[ss][dl2][n1]);
        if (j == 0) ys += sc[ss][dl2];
    }
    ys += __shfl_down_sync(0xFFFFFFFFu, ys, 4);
    ys += __shfl_down_sync(0xFFFFFFFFu, ys, 2);
    ys += __shfl_down_sync(0xFFFFFFFFu, ys, 1);
    if (j == 0) g_ybar[(size_t)b * DINNER + d0 + dl2] = ys * (1.f / (float)SEQLEN);
}

// ---------------------------------------------------------------------------
// K5: head
// ---------------------------------------------------------------------------
__global__ __launch_bounds__(256) void k5_head(const float* __restrict__ W_out,
                                               const float* __restrict__ W_outfc,
                                               const float* __restrict__ b_outfc,
                                               const float* __restrict__ W_mu,
                                               const float* __restrict__ b_mu,
                                               const float* __restrict__ W_sigma,
                                               const float* __restrict__ b_sigma,
                                               float* __restrict__ out) {
    const int b = blockIdx.x;
    const int tid = threadIdx.x;
    __shared__ float sy[DINNER];
    __shared__ float se[DMODEL];
    __shared__ float sxv[DIMIN];

    sy[tid] = g_ybar[b * DINNER + tid];
    sy[tid + 256] = g_ybar[b * DINNER + tid + 256];
    __syncthreads();

    {
        float e = 0.f;
        const float* wr = &W_out[tid * DINNER];
        for (int dd = 0; dd < DINNER; dd++) e = fmaf(sy[dd], wr[dd], e);
        se[tid] = e;
    }
    __syncthreads();

    {
        float a = b_outfc[tid];
        const float* wr = &W_outfc[tid * DMODEL];
        for (int k = 0; k < DMODEL; k++) a = fmaf(se[k], wr[k], a);
        float t = tanhf(a);
        float xv = (t > 0.f) ? t : expm1f(t);
        sxv[tid] = xv;
        out[b * DIMIN + tid] = xv;
    }
    __syncthreads();

    float* out_mu    = out + BATCH * DIMIN;
    float* out_sigma = out + BATCH * DIMIN + BATCH * DIMOUT;
    if (tid < DIMOUT) {
        float a = b_mu[tid];
        const float* wr = &W_mu[tid * DIMIN];
        for (int k = 0; k < DIMIN; k++) a = fmaf(sxv[k], wr[k], a);
        out_mu[b * DIMOUT + tid] = a;
    } else if (tid < 2 * DIMOUT) {
        int o = tid - DIMOUT;
        float a = b_sigma[o];
        const float* wr = &W_sigma[o * DIMIN];
        for (int k = 0; k < DIMIN; k++) a = fmaf(sxv[k], wr[k], a);
        float el = (a > 0.f) ? a : expm1f(a);
        out_sigma[b * DIMOUT + o] = el + 1.f + 1e-14f;
    }
}

// ---------------------------------------------------------------------------
extern "C" void kernel_launch(void* const* d_in, const int* in_sizes, int n_in,
                              void* d_out, int out_size) {
    const float* input   = (const float*)d_in[0];
    const float* W_in    = (const float*)d_in[1];
    const float* conv_w  = (const float*)d_in[2];
    const float* conv_b  = (const float*)d_in[3];
    const float* W_xproj = (const float*)d_in[4];
    const float* W_dt    = (const float*)d_in[5];
    const float* b_dt    = (const float*)d_in[6];
    const float* A_log   = (const float*)d_in[7];
    const float* D_param = (const float*)d_in[8];
    const float* W_out   = (const float*)d_in[9];
    const float* W_outfc = (const float*)d_in[10];
    const float* b_outfc = (const float*)d_in[11];
    const float* W_mu    = (const float*)d_in[12];
    const float* b_mu    = (const float*)d_in[13];
    const float* W_sigma = (const float*)d_in[14];
    const float* b_sigma = (const float*)d_in[15];
    float* out = (float*)d_out;

    k1_gemm<<<dim3(1024 / 128, BL / 128), 256>>>(input, W_in);
    k3_convproj<<<BL / K3ROWS, 512>>>(conv_w, conv_b, W_xproj, W_dt, b_dt);
    k4_scan<<<dim3(BATCH, DINNER / 16), 128>>>(A_log, D_param);
    k5_head<<<BATCH, 256>>>(W_out, W_outfc, b_outfc, W_mu, b_mu, W_sigma, b_sigma, out);
}

// round 6
// speedup vs baseline: 1.0688x; 1.0688x over previous
#include <cuda_runtime.h>
#include <math.h>
#include <stdint.h>

// Problem dims
#define BATCH 64
#define SEQLEN 256
#define DMODEL 256
#define DINNER 512
#define DSTATE 16
#define DTRANK 16
#define DCONV 4
#define DIMIN 256
#define DIMOUT 64
#define BL (BATCH * SEQLEN)      // 16384
#define SEG 8
#define LSEG (SEQLEN / SEG)      // 32

// Scratch (device globals: no cudaMalloc allowed)
__device__ float g_xin[BL * DINNER];
__device__ float g_z[BL * DINNER];
__device__ float g_xc[BL * DINNER];
__device__ float g_delta[BL * DINNER];
__device__ float g_Bm[BL * DSTATE];
__device__ float g_Cm[BL * DSTATE];
__device__ float g_ybar[BATCH * DINNER];
// segment scan partials
__device__ float g_segW[SEG * BATCH * DINNER * DSTATE];
__device__ float g_segP[SEG * BATCH * DINNER * DSTATE];
__device__ float g_segV[SEG * BATCH * DINNER * DSTATE];
__device__ float g_segc[SEG * BATCH * DINNER];

// ---------------------------------------------------------------------------
// K1: xz = input @ W_in^T ; split into x_in and z   (R2-proven SGEMM)
// ---------------------------------------------------------------------------
__global__ __launch_bounds__(256) void k1_gemm(const float* __restrict__ X,
                                               const float* __restrict__ W) {
    __shared__ float As[16][132];
    __shared__ float Bs[16][132];

    const int m0 = blockIdx.y * 128;
    const int n0 = blockIdx.x * 128;
    const int tid = threadIdx.x;
    const int tx = tid & 15;
    const int ty = tid >> 4;

    float acc[8][8];
#pragma unroll
    for (int i = 0; i < 8; i++)
#pragma unroll
        for (int j = 0; j < 8; j++) acc[i][j] = 0.f;

    for (int k0 = 0; k0 < 256; k0 += 16) {
#pragma unroll
        for (int i = 0; i < 2; i++) {
            int f = tid + i * 256;
            int m = f >> 2;
            int k4 = (f & 3) * 4;
            float4 va = *reinterpret_cast<const float4*>(&X[(m0 + m) * 256 + k0 + k4]);
            As[k4 + 0][m] = va.x; As[k4 + 1][m] = va.y;
            As[k4 + 2][m] = va.z; As[k4 + 3][m] = va.w;
            float4 vb = *reinterpret_cast<const float4*>(&W[(n0 + m) * 256 + k0 + k4]);
            Bs[k4 + 0][m] = vb.x; Bs[k4 + 1][m] = vb.y;
            Bs[k4 + 2][m] = vb.z; Bs[k4 + 3][m] = vb.w;
        }
        __syncthreads();

#pragma unroll
        for (int kk = 0; kk < 16; kk++) {
            float a[8], b[8];
            *reinterpret_cast<float4*>(&a[0]) = *reinterpret_cast<const float4*>(&As[kk][ty * 8]);
            *reinterpret_cast<float4*>(&a[4]) = *reinterpret_cast<const float4*>(&As[kk][ty * 8 + 4]);
            *reinterpret_cast<float4*>(&b[0]) = *reinterpret_cast<const float4*>(&Bs[kk][tx * 8]);
            *reinterpret_cast<float4*>(&b[4]) = *reinterpret_cast<const float4*>(&Bs[kk][tx * 8 + 4]);
#pragma unroll
            for (int i = 0; i < 8; i++)
#pragma unroll
                for (int j = 0; j < 8; j++) acc[i][j] = fmaf(a[i], b[j], acc[i][j]);
        }
        __syncthreads();
    }

    float* dstbase = (n0 < DINNER) ? g_xin : g_z;
    const int ncol = (n0 < DINNER) ? (n0 + tx * 8) : (n0 - DINNER + tx * 8);
#pragma unroll
    for (int i = 0; i < 8; i++) {
        int m = m0 + ty * 8 + i;
        float4 o0 = make_float4(acc[i][0], acc[i][1], acc[i][2], acc[i][3]);
        float4 o1 = make_float4(acc[i][4], acc[i][5], acc[i][6], acc[i][7]);
        *reinterpret_cast<float4*>(&dstbase[m * DINNER + ncol]) = o0;
        *reinterpret_cast<float4*>(&dstbase[m * DINNER + ncol + 4]) = o1;
    }
}

// ---------------------------------------------------------------------------
// K3 (fused conv + proj): conv(width4,causal)+bias+SiLU in smem, write g_xc,
// then x_dbl = xc @ W_xproj^T; split dt/B/C; delta = softplus(dt@W_dt^T+b_dt)
// ---------------------------------------------------------------------------
#define K3ROWS 16
__global__ __launch_bounds__(512) void k3_convproj(const float* __restrict__ cw,
                                                   const float* __restrict__ cb,
                                                   const float* __restrict__ Wx,
                                                   const float* __restrict__ Wdt,
                                                   const float* __restrict__ bdt) {
    const int bl0 = blockIdx.x * K3ROWS;
    const int l0 = bl0 & (SEQLEN - 1);
    __shared__ float sxin[K3ROWS + 3][DINNER];
    __shared__ float sdbl[K3ROWS][48];
    const int tid = threadIdx.x;

#pragma unroll
    for (int j = 0; j < K3ROWS + 3; j++) {
        int bl = bl0 - 3 + j;
        sxin[j][tid] = (l0 + j >= 3) ? g_xin[(size_t)bl * DINNER + tid] : 0.f;
    }

    const float w0 = cw[tid * 4 + 0], w1 = cw[tid * 4 + 1];
    const float w2 = cw[tid * 4 + 2], w3 = cw[tid * 4 + 3];
    const float bias = cb[tid];
#pragma unroll
    for (int r = 0; r < K3ROWS; r++) {
        float sum = bias;
        sum = fmaf(sxin[r + 0][tid], w0, sum);
        sum = fmaf(sxin[r + 1][tid], w1, sum);
        sum = fmaf(sxin[r + 2][tid], w2, sum);
        sum = fmaf(sxin[r + 3][tid], w3, sum);
        float xc = sum / (1.f + expf(-sum));
        sxin[r][tid] = xc;
        g_xc[(size_t)(bl0 + r) * DINNER + tid] = xc;
    }
    __syncthreads();

    const int w = tid >> 5, lane = tid & 31;
#pragma unroll
    for (int oi = 0; oi < 3; oi++) {
        const int o = w + oi * 16;
        float s[K3ROWS];
#pragma unroll
        for (int r = 0; r < K3ROWS; r++) s[r] = 0.f;
#pragma unroll
        for (int it = 0; it < DINNER / 128; it++) {
            const int k = it * 128 + lane * 4;
            float4 wv = *reinterpret_cast<const float4*>(&Wx[o * DINNER + k]);
#pragma unroll
            for (int r = 0; r < K3ROWS; r++) {
                s[r] = fmaf(sxin[r][k + 0], wv.x, s[r]);
                s[r] = fmaf(sxin[r][k + 1], wv.y, s[r]);
                s[r] = fmaf(sxin[r][k + 2], wv.z, s[r]);
                s[r] = fmaf(sxin[r][k + 3], wv.w, s[r]);
            }
        }
#pragma unroll
        for (int off = 16; off; off >>= 1)
#pragma unroll
            for (int r = 0; r < K3ROWS; r++) s[r] += __shfl_down_sync(0xFFFFFFFFu, s[r], off);
        if (lane == 0) {
#pragma unroll
            for (int r = 0; r < K3ROWS; r++) sdbl[r][o] = s[r];
        }
    }
    __syncthreads();

    if (tid < K3ROWS * 16) {
        int r = tid >> 4, n = tid & 15;
        g_Bm[(size_t)(bl0 + r) * DSTATE + n] = sdbl[r][DTRANK + n];
        g_Cm[(size_t)(bl0 + r) * DSTATE + n] = sdbl[r][DTRANK + DSTATE + n];
    }

    float bv = bdt[tid];
    float wr[DTRANK];
#pragma unroll
    for (int i = 0; i < DTRANK; i++) wr[i] = Wdt[tid * DTRANK + i];
#pragma unroll
    for (int r = 0; r < K3ROWS; r++) {
        float acc = bv;
#pragma unroll
        for (int i = 0; i < DTRANK; i++) acc = fmaf(sdbl[r][i], wr[i], acc);
        float sp = fmaxf(acc, 0.f) + log1pf(expf(-fabsf(acc)));
        g_delta[(size_t)(bl0 + r) * DINNER + tid] = sp;
    }
}

// ---------------------------------------------------------------------------
// K4a: segmented selective scan (R3-proven). Grid (64, 4, SEG), 128 threads.
// ---------------------------------------------------------------------------
template <bool FAST>
__device__ __forceinline__ void seg_scan_body(
    int b, int d, int s, const float* __restrict__ A,
    float Dp, const float* __restrict__ sB, const float* __restrict__ sC)
{
    float P[DSTATE], V[DSTATE], Wc[DSTATE];
#pragma unroll
    for (int n = 0; n < DSTATE; n++) { P[n] = 1.f; V[n] = 0.f; Wc[n] = 0.f; }
    float c = 0.f;
    const float A0 = A[0];

    const int l0 = s * LSEG;
    const float* pdelta = g_delta + ((size_t)(b * SEQLEN + l0)) * DINNER + d;
    const float* pxc    = g_xc    + ((size_t)(b * SEQLEN + l0)) * DINNER + d;
    const float* pz     = g_z     + ((size_t)(b * SEQLEN + l0)) * DINNER + d;

    float dt  = pdelta[0];
    float xcv = pxc[0];
    float zv  = pz[0];

#pragma unroll 4
    for (int l = 0; l < LSEG; l++) {
        float dtn = 0.f, xcn = 0.f, zvn = 0.f;
        if (l + 1 < LSEG) {
            dtn = pdelta[(l + 1) * DINNER];
            xcn = pxc[(l + 1) * DINNER];
            zvn = pz[(l + 1) * DINNER];
        }
        float gate = __fdividef(zv, 1.f + __expf(-zv));
        float du = dt * xcv;
        float yl = 0.f;

        float dA[DSTATE];
        if (FAST) {
            float r  = __expf(dt * A0);
            float r2 = r * r;
            float r4 = r2 * r2;
            float r8 = r4 * r4;
            dA[0]  = r;          dA[1]  = r2;         dA[2]  = r2 * r;     dA[3]  = r4;
            dA[4]  = r4 * r;     dA[5]  = r4 * r2;    dA[6]  = r4 * dA[2]; dA[7]  = r8;
            dA[8]  = r8 * r;     dA[9]  = r8 * r2;    dA[10] = r8 * dA[2]; dA[11] = r8 * r4;
            dA[12] = r8 * dA[4]; dA[13] = r8 * dA[5]; dA[14] = r8 * dA[6]; dA[15] = r8 * r8;
        } else {
#pragma unroll
            for (int n = 0; n < DSTATE; n++) dA[n] = __expf(dt * A[n]);
        }

#pragma unroll
        for (int n = 0; n < DSTATE; n++) {
            float Bn = sB[l * DSTATE + n];
            float Cn = sC[l * DSTATE + n];
            P[n] *= dA[n];
            V[n] = fmaf(dA[n], V[n], du * Bn);
            yl = fmaf(V[n], Cn, yl);
            Wc[n] = fmaf(gate * Cn, P[n], Wc[n]);
        }
        c = fmaf(gate, fmaf(xcv, Dp, yl), c);
        dt = dtn; xcv = xcn; zv = zvn;
    }

    size_t base = (((size_t)s * BATCH + b) * DINNER + d) * DSTATE;
#pragma unroll
    for (int q = 0; q < DSTATE; q += 4) {
        *reinterpret_cast<float4*>(&g_segP[base + q]) = make_float4(P[q], P[q+1], P[q+2], P[q+3]);
        *reinterpret_cast<float4*>(&g_segV[base + q]) = make_float4(V[q], V[q+1], V[q+2], V[q+3]);
        *reinterpret_cast<float4*>(&g_segW[base + q]) = make_float4(Wc[q], Wc[q+1], Wc[q+2], Wc[q+3]);
    }
    g_segc[((size_t)s * BATCH + b) * DINNER + d] = c;
}

__global__ __launch_bounds__(128) void k4_seg(const float* __restrict__ A_log,
                                              const float* __restrict__ D_param) {
    const int b = blockIdx.x;
    const int d = blockIdx.y * 128 + threadIdx.x;
    const int s = blockIdx.z;

    __shared__ float sB[LSEG * DSTATE];
    __shared__ float sC[LSEG * DSTATE];
    {
        const float* gB = g_Bm + ((size_t)b * SEQLEN + s * LSEG) * DSTATE;
        const float* gC = g_Cm + ((size_t)b * SEQLEN + s * LSEG) * DSTATE;
        for (int i = threadIdx.x * 4; i < LSEG * DSTATE; i += 128 * 4) {
            *reinterpret_cast<float4*>(&sB[i]) = *reinterpret_cast<const float4*>(&gB[i]);
            *reinterpret_cast<float4*>(&sC[i]) = *reinterpret_cast<const float4*>(&gC[i]);
        }
    }
    __syncthreads();

    float A[DSTATE];
    bool fast = true;
#pragma unroll
    for (int n = 0; n < DSTATE; n++) {
        A[n] = -expf(A_log[d * DSTATE + n]);
        fast = fast && (fabsf(A[n] - (float)(n + 1) * A[0]) <= 1e-4f * fabsf(A[n]));
    }
    const float Dp = D_param[d];

    if (fast) seg_scan_body<true >(b, d, s, A, Dp, sB, sC);
    else      seg_scan_body<false>(b, d, s, A, Dp, sB, sC);
}

// K4b: combine segments. Grid (64,4), 128 threads.
__global__ __launch_bounds__(128) void k4_combine() {
    const int b = blockIdx.x;
    const int d = blockIdx.y * 128 + threadIdx.x;

    float h[DSTATE];
#pragma unroll
    for (int n = 0; n < DSTATE; n++) h[n] = 0.f;
    float ysum = 0.f;

#pragma unroll
    for (int s = 0; s < SEG; s++) {
        size_t base = (((size_t)s * BATCH + b) * DINNER + d) * DSTATE;
        float dot = g_segc[((size_t)s * BATCH + b) * DINNER + d];
#pragma unroll
        for (int q = 0; q < DSTATE; q += 4) {
            float4 Wv = *reinterpret_cast<const float4*>(&g_segW[base + q]);
            float4 Pv = *reinterpret_cast<const float4*>(&g_segP[base + q]);
            float4 Vv = *reinterpret_cast<const float4*>(&g_segV[base + q]);
            dot = fmaf(Wv.x, h[q+0], dot);
            dot = fmaf(Wv.y, h[q+1], dot);
            dot = fmaf(Wv.z, h[q+2], dot);
            dot = fmaf(Wv.w, h[q+3], dot);
            h[q+0] = fmaf(Pv.x, h[q+0], Vv.x);
            h[q+1] = fmaf(Pv.y, h[q+1], Vv.y);
            h[q+2] = fmaf(Pv.z, h[q+2], Vv.z);
            h[q+3] = fmaf(Pv.w, h[q+3], Vv.w);
        }
        ysum += dot;
    }
    g_ybar[(size_t)b * DINNER + d] = ysum * (1.f / (float)SEQLEN);
}

// ---------------------------------------------------------------------------
// K5: head, warp-cooperative coalesced dots.
// Block per batch, 256 threads (8 warps). Lanes split k with float4 reads.
// ---------------------------------------------------------------------------
__device__ __forceinline__ float warp_dot(const float* __restrict__ wrow,
                                          const float* __restrict__ svec,
                                          int K, int lane) {
    float s = 0.f;
    for (int k = lane * 4; k < K; k += 128) {
        float4 wv = *reinterpret_cast<const float4*>(&wrow[k]);
        s = fmaf(svec[k + 0], wv.x, s);
        s = fmaf(svec[k + 1], wv.y, s);
        s = fmaf(svec[k + 2], wv.z, s);
        s = fmaf(svec[k + 3], wv.w, s);
    }
#pragma unroll
    for (int off = 16; off; off >>= 1) s += __shfl_down_sync(0xFFFFFFFFu, s, off);
    return s;
}

__global__ __launch_bounds__(256) void k5_head(const float* __restrict__ W_out,
                                               const float* __restrict__ W_outfc,
                                               const float* __restrict__ b_outfc,
                                               const float* __restrict__ W_mu,
                                               const float* __restrict__ b_mu,
                                               const float* __restrict__ W_sigma,
                                               const float* __restrict__ b_sigma,
                                               float* __restrict__ out) {
    const int b = blockIdx.x;
    const int tid = threadIdx.x;
    const int w = tid >> 5, lane = tid & 31;
    __shared__ float sy[DINNER];
    __shared__ float se[DMODEL];
    __shared__ float sxv[DIMIN];

    sy[tid] = g_ybar[(size_t)b * DINNER + tid];
    sy[tid + 256] = g_ybar[(size_t)b * DINNER + tid + 256];
    __syncthreads();

    // e[o] = ybar . W_out[o,:]   (256 outputs, 32 per warp)
#pragma unroll
    for (int oi = 0; oi < 32; oi++) {
        const int o = w + oi * 8;
        float s = warp_dot(&W_out[o * DINNER], sy, DINNER, lane);
        if (lane == 0) se[o] = s;
    }
    __syncthreads();

    // x[o] = elu(tanh(e . W_outfc[o,:] + b))
#pragma unroll
    for (int oi = 0; oi < 32; oi++) {
        const int o = w + oi * 8;
        float s = warp_dot(&W_outfc[o * DMODEL], se, DMODEL, lane);
        if (lane == 0) {
            s += b_outfc[o];
            float t = tanhf(s);
            float xv = (t > 0.f) ? t : expm1f(t);
            sxv[o] = xv;
            out[(size_t)b * DIMIN + o] = xv;
        }
    }
    __syncthreads();

    // mu / sigma (128 outputs, 16 per warp)
    float* out_mu    = out + BATCH * DIMIN;
    float* out_sigma = out + BATCH * DIMIN + BATCH * DIMOUT;
#pragma unroll
    for (int oi = 0; oi < 16; oi++) {
        const int o = w + oi * 8;
        if (o < DIMOUT) {
            float s = warp_dot(&W_mu[o * DIMIN], sxv, DIMIN, lane);
            if (lane == 0) out_mu[(size_t)b * DIMOUT + o] = s + b_mu[o];
        } else {
            const int o2 = o - DIMOUT;
            float s = warp_dot(&W_sigma[o2 * DIMIN], sxv, DIMIN, lane);
            if (lane == 0) {
                s += b_sigma[o2];
                float el = (s > 0.f) ? s : expm1f(s);
                out_sigma[(size_t)b * DIMOUT + o2] = el + 1.f + 1e-14f;
            }
        }
    }
}

// ---------------------------------------------------------------------------
extern "C" void kernel_launch(void* const* d_in, const int* in_sizes, int n_in,
                              void* d_out, int out_size) {
    const float* input   = (const float*)d_in[0];
    const float* W_in    = (const float*)d_in[1];
    const float* conv_w  = (const float*)d_in[2];
    const float* conv_b  = (const float*)d_in[3];
    const float* W_xproj = (const float*)d_in[4];
    const float* W_dt    = (const float*)d_in[5];
    const float* b_dt    = (const float*)d_in[6];
    const float* A_log   = (const float*)d_in[7];
    const float* D_param = (const float*)d_in[8];
    const float* W_out   = (const float*)d_in[9];
    const float* W_outfc = (const float*)d_in[10];
    const float* b_outfc = (const float*)d_in[11];
    const float* W_mu    = (const float*)d_in[12];
    const float* b_mu    = (const float*)d_in[13];
    const float* W_sigma = (const float*)d_in[14];
    const float* b_sigma = (const float*)d_in[15];
    float* out = (float*)d_out;

    k1_gemm<<<dim3(1024 / 128, BL / 128), 256>>>(input, W_in);
    k3_convproj<<<BL / K3ROWS, 512>>>(conv_w, conv_b, W_xproj, W_dt, b_dt);
    k4_seg<<<dim3(BATCH, DINNER / 128, SEG), 128>>>(A_log, D_param);
    k4_combine<<<dim3(BATCH, DINNER / 128), 128>>>();
    k5_head<<<BATCH, 256>>>(W_out, W_outfc, b_outfc, W_mu, b_mu, W_sigma, b_sigma, out);
}

// round 7
// speedup vs baseline: 1.4041x; 1.3137x over previous
#include <cuda_runtime.h>
#include <math.h>
#include <stdint.h>

// Problem dims
#define BATCH 64
#define SEQLEN 256
#define DMODEL 256
#define DINNER 512
#define DSTATE 16
#define DTRANK 16
#define DCONV 4
#define DIMIN 256
#define DIMOUT 64
#define BL (BATCH * SEQLEN)      // 16384
#define SEG 8
#define LSEG (SEQLEN / SEG)      // 32

// Scratch (device globals: no cudaMalloc allowed)
__device__ float g_xin[BL * DINNER];
__device__ float g_z[BL * DINNER];
__device__ float g_xc[BL * DINNER];
__device__ float g_delta[BL * DINNER];
__device__ float g_Bm[BL * DSTATE];
__device__ float g_Cm[BL * DSTATE];
__device__ float g_ybar[BATCH * DINNER];
// segment scan partials
__device__ float g_segW[SEG * BATCH * DINNER * DSTATE];
__device__ float g_segP[SEG * BATCH * DINNER * DSTATE];
__device__ float g_segV[SEG * BATCH * DINNER * DSTATE];
__device__ float g_segc[SEG * BATCH * DINNER];

// ---------------------------------------------------------------------------
// K1: xz = input @ W_in^T ; split into x_in and z   (R2-proven SGEMM)
// M=16384, N=1024, K=256. BM=BN=128, BK=16, 256 threads, 8x8 micro-tile.
// ---------------------------------------------------------------------------
__global__ __launch_bounds__(256) void k1_gemm(const float* __restrict__ X,
                                               const float* __restrict__ W) {
    __shared__ float As[16][132];
    __shared__ float Bs[16][132];

    const int m0 = blockIdx.y * 128;
    const int n0 = blockIdx.x * 128;
    const int tid = threadIdx.x;
    const int tx = tid & 15;
    const int ty = tid >> 4;

    float acc[8][8];
#pragma unroll
    for (int i = 0; i < 8; i++)
#pragma unroll
        for (int j = 0; j < 8; j++) acc[i][j] = 0.f;

    for (int k0 = 0; k0 < 256; k0 += 16) {
#pragma unroll
        for (int i = 0; i < 2; i++) {
            int f = tid + i * 256;
            int m = f >> 2;
            int k4 = (f & 3) * 4;
            float4 va = *reinterpret_cast<const float4*>(&X[(m0 + m) * 256 + k0 + k4]);
            As[k4 + 0][m] = va.x; As[k4 + 1][m] = va.y;
            As[k4 + 2][m] = va.z; As[k4 + 3][m] = va.w;
            float4 vb = *reinterpret_cast<const float4*>(&W[(n0 + m) * 256 + k0 + k4]);
            Bs[k4 + 0][m] = vb.x; Bs[k4 + 1][m] = vb.y;
            Bs[k4 + 2][m] = vb.z; Bs[k4 + 3][m] = vb.w;
        }
        __syncthreads();

#pragma unroll
        for (int kk = 0; kk < 16; kk++) {
            float a[8], b[8];
            *reinterpret_cast<float4*>(&a[0]) = *reinterpret_cast<const float4*>(&As[kk][ty * 8]);
            *reinterpret_cast<float4*>(&a[4]) = *reinterpret_cast<const float4*>(&As[kk][ty * 8 + 4]);
            *reinterpret_cast<float4*>(&b[0]) = *reinterpret_cast<const float4*>(&Bs[kk][tx * 8]);
            *reinterpret_cast<float4*>(&b[4]) = *reinterpret_cast<const float4*>(&Bs[kk][tx * 8 + 4]);
#pragma unroll
            for (int i = 0; i < 8; i++)
#pragma unroll
                for (int j = 0; j < 8; j++) acc[i][j] = fmaf(a[i], b[j], acc[i][j]);
        }
        __syncthreads();
    }

    float* dstbase = (n0 < DINNER) ? g_xin : g_z;
    const int ncol = (n0 < DINNER) ? (n0 + tx * 8) : (n0 - DINNER + tx * 8);
#pragma unroll
    for (int i = 0; i < 8; i++) {
        int m = m0 + ty * 8 + i;
        float4 o0 = make_float4(acc[i][0], acc[i][1], acc[i][2], acc[i][3]);
        float4 o1 = make_float4(acc[i][4], acc[i][5], acc[i][6], acc[i][7]);
        *reinterpret_cast<float4*>(&dstbase[m * DINNER + ncol]) = o0;
        *reinterpret_cast<float4*>(&dstbase[m * DINNER + ncol + 4]) = o1;
    }
}

// ---------------------------------------------------------------------------
// K2: causal depthwise conv (width 4) + bias + SiLU   (R2-proven)
// ---------------------------------------------------------------------------
__global__ __launch_bounds__(256) void k2_conv(const float* __restrict__ cw,
                                               const float* __restrict__ cb) {
    int idx = blockIdx.x * blockDim.x + threadIdx.x;
    if (idx >= BL * DINNER) return;
    int d = idx % DINNER;
    int l = (idx / DINNER) % SEQLEN;
    int b = idx / (DINNER * SEQLEN);

    float s = cb[d];
#pragma unroll
    for (int j = 0; j < DCONV; j++) {
        int li = l - (DCONV - 1) + j;
        if (li >= 0) s = fmaf(g_xin[(b * SEQLEN + li) * DINNER + d], cw[d * DCONV + j], s);
    }
    float sig = 1.f / (1.f + expf(-s));
    g_xc[idx] = s * sig;
}

// ---------------------------------------------------------------------------
// K3: x_dbl = xc @ W_xproj^T (48 out); split dt/B/C;
// delta = softplus(dt@W_dt^T + b_dt).  (R2-proven 8-row version, verbatim)
// ---------------------------------------------------------------------------
#define K3ROWS 8
__global__ __launch_bounds__(512) void k3_proj(const float* __restrict__ Wx,
                                               const float* __restrict__ Wdt,
                                               const float* __restrict__ bdt) {
    const int bl0 = blockIdx.x * K3ROWS;
    __shared__ float sx[K3ROWS][DINNER];
    __shared__ float sdbl[K3ROWS][48];
    const int tid = threadIdx.x;

#pragma unroll
    for (int r = 0; r < K3ROWS; r++) sx[r][tid] = g_xc[(size_t)(bl0 + r) * DINNER + tid];
    __syncthreads();

    const int w = tid >> 5, lane = tid & 31;
    for (int o = w; o < 48; o += 16) {
        float s[K3ROWS];
#pragma unroll
        for (int r = 0; r < K3ROWS; r++) s[r] = 0.f;
        for (int k = lane; k < DINNER; k += 32) {
            float wv = Wx[o * DINNER + k];
#pragma unroll
            for (int r = 0; r < K3ROWS; r++) s[r] = fmaf(sx[r][k], wv, s[r]);
        }
#pragma unroll
        for (int off = 16; off; off >>= 1)
#pragma unroll
            for (int r = 0; r < K3ROWS; r++) s[r] += __shfl_down_sync(0xFFFFFFFFu, s[r], off);
        if (lane == 0) {
#pragma unroll
            for (int r = 0; r < K3ROWS; r++) sdbl[r][o] = s[r];
        }
    }
    __syncthreads();

    if (tid < K3ROWS * 16) {
        int r = tid >> 4, n = tid & 15;
        g_Bm[(size_t)(bl0 + r) * DSTATE + n] = sdbl[r][DTRANK + n];
    } else if (tid < 2 * K3ROWS * 16) {
        int t = tid - K3ROWS * 16;
        int r = t >> 4, n = t & 15;
        g_Cm[(size_t)(bl0 + r) * DSTATE + n] = sdbl[r][DTRANK + DSTATE + n];
    }

    float bv = bdt[tid];
    float wr[DTRANK];
#pragma unroll
    for (int i = 0; i < DTRANK; i++) wr[i] = Wdt[tid * DTRANK + i];
#pragma unroll
    for (int r = 0; r < K3ROWS; r++) {
        float acc = bv;
#pragma unroll
        for (int i = 0; i < DTRANK; i++) acc = fmaf(sdbl[r][i], wr[i], acc);
        float sp = fmaxf(acc, 0.f) + log1pf(expf(-fabsf(acc)));
        g_delta[(size_t)(bl0 + r) * DINNER + tid] = sp;
    }
}

// ---------------------------------------------------------------------------
// K4a: segmented selective scan (R3-proven). Grid (64, 4, SEG), 128 threads.
// ---------------------------------------------------------------------------
template <bool FAST>
__device__ __forceinline__ void seg_scan_body(
    int b, int d, int s, const float* __restrict__ A,
    float Dp, const float* __restrict__ sB, const float* __restrict__ sC)
{
    float P[DSTATE], V[DSTATE], Wc[DSTATE];
#pragma unroll
    for (int n = 0; n < DSTATE; n++) { P[n] = 1.f; V[n] = 0.f; Wc[n] = 0.f; }
    float c = 0.f;
    const float A0 = A[0];

    const int l0 = s * LSEG;
    const float* pdelta = g_delta + ((size_t)(b * SEQLEN + l0)) * DINNER + d;
    const float* pxc    = g_xc    + ((size_t)(b * SEQLEN + l0)) * DINNER + d;
    const float* pz     = g_z     + ((size_t)(b * SEQLEN + l0)) * DINNER + d;

    float dt  = pdelta[0];
    float xcv = pxc[0];
    float zv  = pz[0];

#pragma unroll 4
    for (int l = 0; l < LSEG; l++) {
        float dtn = 0.f, xcn = 0.f, zvn = 0.f;
        if (l + 1 < LSEG) {
            dtn = pdelta[(l + 1) * DINNER];
            xcn = pxc[(l + 1) * DINNER];
            zvn = pz[(l + 1) * DINNER];
        }
        float gate = __fdividef(zv, 1.f + __expf(-zv));
        float du = dt * xcv;
        float yl = 0.f;

        float dA[DSTATE];
        if (FAST) {
            float r  = __expf(dt * A0);
            float r2 = r * r;
            float r4 = r2 * r2;
            float r8 = r4 * r4;
            dA[0]  = r;          dA[1]  = r2;         dA[2]  = r2 * r;     dA[3]  = r4;
            dA[4]  = r4 * r;     dA[5]  = r4 * r2;    dA[6]  = r4 * dA[2]; dA[7]  = r8;
            dA[8]  = r8 * r;     dA[9]  = r8 * r2;    dA[10] = r8 * dA[2]; dA[11] = r8 * r4;
            dA[12] = r8 * dA[4]; dA[13] = r8 * dA[5]; dA[14] = r8 * dA[6]; dA[15] = r8 * r8;
        } else {
#pragma unroll
            for (int n = 0; n < DSTATE; n++) dA[n] = __expf(dt * A[n]);
        }

#pragma unroll
        for (int n = 0; n < DSTATE; n++) {
            float Bn = sB[l * DSTATE + n];
            float Cn = sC[l * DSTATE + n];
            P[n] *= dA[n];
            V[n] = fmaf(dA[n], V[n], du * Bn);
            yl = fmaf(V[n], Cn, yl);
            Wc[n] = fmaf(gate * Cn, P[n], Wc[n]);
        }
        c = fmaf(gate, fmaf(xcv, Dp, yl), c);
        dt = dtn; xcv = xcn; zv = zvn;
    }

    size_t base = (((size_t)s * BATCH + b) * DINNER + d) * DSTATE;
#pragma unroll
    for (int q = 0; q < DSTATE; q += 4) {
        *reinterpret_cast<float4*>(&g_segP[base + q]) = make_float4(P[q], P[q+1], P[q+2], P[q+3]);
        *reinterpret_cast<float4*>(&g_segV[base + q]) = make_float4(V[q], V[q+1], V[q+2], V[q+3]);
        *reinterpret_cast<float4*>(&g_segW[base + q]) = make_float4(Wc[q], Wc[q+1], Wc[q+2], Wc[q+3]);
    }
    g_segc[((size_t)s * BATCH + b) * DINNER + d] = c;
}

__global__ __launch_bounds__(128) void k4_seg(const float* __restrict__ A_log,
                                              const float* __restrict__ D_param) {
    const int b = blockIdx.x;
    const int d = blockIdx.y * 128 + threadIdx.x;
    const int s = blockIdx.z;

    __shared__ float sB[LSEG * DSTATE];
    __shared__ float sC[LSEG * DSTATE];
    {
        const float* gB = g_Bm + ((size_t)b * SEQLEN + s * LSEG) * DSTATE;
        const float* gC = g_Cm + ((size_t)b * SEQLEN + s * LSEG) * DSTATE;
        for (int i = threadIdx.x * 4; i < LSEG * DSTATE; i += 128 * 4) {
            *reinterpret_cast<float4*>(&sB[i]) = *reinterpret_cast<const float4*>(&gB[i]);
            *reinterpret_cast<float4*>(&sC[i]) = *reinterpret_cast<const float4*>(&gC[i]);
        }
    }
    __syncthreads();

    float A[DSTATE];
    bool fast = true;
#pragma unroll
    for (int n = 0; n < DSTATE; n++) {
        A[n] = -expf(A_log[d * DSTATE + n]);
        fast = fast && (fabsf(A[n] - (float)(n + 1) * A[0]) <= 1e-4f * fabsf(A[n]));
    }
    const float Dp = D_param[d];

    if (fast) seg_scan_body<true >(b, d, s, A, Dp, sB, sC);
    else      seg_scan_body<false>(b, d, s, A, Dp, sB, sC);
}

// K4b: combine segments. Grid (64,4), 128 threads.
__global__ __launch_bounds__(128) void k4_combine() {
    const int b = blockIdx.x;
    const int d = blockIdx.y * 128 + threadIdx.x;

    float h[DSTATE];
#pragma unroll
    for (int n = 0; n < DSTATE; n++) h[n] = 0.f;
    float ysum = 0.f;

#pragma unroll
    for (int s = 0; s < SEG; s++) {
        size_t base = (((size_t)s * BATCH + b) * DINNER + d) * DSTATE;
        float dot = g_segc[((size_t)s * BATCH + b) * DINNER + d];
#pragma unroll
        for (int q = 0; q < DSTATE; q += 4) {
            float4 Wv = *reinterpret_cast<const float4*>(&g_segW[base + q]);
            float4 Pv = *reinterpret_cast<const float4*>(&g_segP[base + q]);
            float4 Vv = *reinterpret_cast<const float4*>(&g_segV[base + q]);
            dot = fmaf(Wv.x, h[q+0], dot);
            dot = fmaf(Wv.y, h[q+1], dot);
            dot = fmaf(Wv.z, h[q+2], dot);
            dot = fmaf(Wv.w, h[q+3], dot);
            h[q+0] = fmaf(Pv.x, h[q+0], Vv.x);
            h[q+1] = fmaf(Pv.y, h[q+1], Vv.y);
            h[q+2] = fmaf(Pv.z, h[q+2], Vv.z);
            h[q+3] = fmaf(Pv.w, h[q+3], Vv.w);
        }
        ysum += dot;
    }
    g_ybar[(size_t)b * DINNER + d] = ysum * (1.f / (float)SEQLEN);
}

// ---------------------------------------------------------------------------
// K5: head, warp-cooperative coalesced dots (R6 version).
// ---------------------------------------------------------------------------
__device__ __forceinline__ float warp_dot(const float* __restrict__ wrow,
                                          const float* __restrict__ svec,
                                          int K, int lane) {
    float s = 0.f;
    for (int k = lane * 4; k < K; k += 128) {
        float4 wv = *reinterpret_cast<const float4*>(&wrow[k]);
        s = fmaf(svec[k + 0], wv.x, s);
        s = fmaf(svec[k + 1], wv.y, s);
        s = fmaf(svec[k + 2], wv.z, s);
        s = fmaf(svec[k + 3], wv.w, s);
    }
#pragma unroll
    for (int off = 16; off; off >>= 1) s += __shfl_down_sync(0xFFFFFFFFu, s, off);
    return s;
}

__global__ __launch_bounds__(256) void k5_head(const float* __restrict__ W_out,
                                               const float* __restrict__ W_outfc,
                                               const float* __restrict__ b_outfc,
                                               const float* __restrict__ W_mu,
                                               const float* __restrict__ b_mu,
                                               const float* __restrict__ W_sigma,
                                               const float* __restrict__ b_sigma,
                                               float* __restrict__ out) {
    const int b = blockIdx.x;
    const int tid = threadIdx.x;
    const int w = tid >> 5, lane = tid & 31;
    __shared__ float sy[DINNER];
    __shared__ float se[DMODEL];
    __shared__ float sxv[DIMIN];

    sy[tid] = g_ybar[(size_t)b * DINNER + tid];
    sy[tid + 256] = g_ybar[(size_t)b * DINNER + tid + 256];
    __syncthreads();

#pragma unroll
    for (int oi = 0; oi < 32; oi++) {
        const int o = w + oi * 8;
        float s = warp_dot(&W_out[o * DINNER], sy, DINNER, lane);
        if (lane == 0) se[o] = s;
    }
    __syncthreads();

#pragma unroll
    for (int oi = 0; oi < 32; oi++) {
        const int o = w + oi * 8;
        float s = warp_dot(&W_outfc[o * DMODEL], se, DMODEL, lane);
        if (lane == 0) {
            s += b_outfc[o];
            float t = tanhf(s);
            float xv = (t > 0.f) ? t : expm1f(t);
            sxv[o] = xv;
            out[(size_t)b * DIMIN + o] = xv;
        }
    }
    __syncthreads();

    float* out_mu    = out + BATCH * DIMIN;
    float* out_sigma = out + BATCH * DIMIN + BATCH * DIMOUT;
#pragma unroll
    for (int oi = 0; oi < 16; oi++) {
        const int o = w + oi * 8;
        if (o < DIMOUT) {
            float s = warp_dot(&W_mu[o * DIMIN], sxv, DIMIN, lane);
            if (lane == 0) out_mu[(size_t)b * DIMOUT + o] = s + b_mu[o];
        } else {
            const int o2 = o - DIMOUT;
            float s = warp_dot(&W_sigma[o2 * DIMIN], sxv, DIMIN, lane);
            if (lane == 0) {
                s += b_sigma[o2];
                float el = (s > 0.f) ? s : expm1f(s);
                out_sigma[(size_t)b * DIMOUT + o2] = el + 1.f + 1e-14f;
            }
        }
    }
}

// ---------------------------------------------------------------------------
extern "C" void kernel_launch(void* const* d_in, const int* in_sizes, int n_in,
                              void* d_out, int out_size) {
    const float* input   = (const float*)d_in[0];
    const float* W_in    = (const float*)d_in[1];
    const float* conv_w  = (const float*)d_in[2];
    const float* conv_b  = (const float*)d_in[3];
    const float* W_xproj = (const float*)d_in[4];
    const float* W_dt    = (const float*)d_in[5];
    const float* b_dt    = (const float*)d_in[6];
    const float* A_log   = (const float*)d_in[7];
    const float* D_param = (const float*)d_in[8];
    const float* W_out   = (const float*)d_in[9];
    const float* W_outfc = (const float*)d_in[10];
    const float* b_outfc = (const float*)d_in[11];
    const float* W_mu    = (const float*)d_in[12];
    const float* b_mu    = (const float*)d_in[13];
    const float* W_sigma = (const float*)d_in[14];
    const float* b_sigma = (const float*)d_in[15];
    float* out = (float*)d_out;

    k1_gemm<<<dim3(1024 / 128, BL / 128), 256>>>(input, W_in);
    k2_conv<<<(BL * DINNER + 255) / 256, 256>>>(conv_w, conv_b);
    k3_proj<<<BL / K3ROWS, 512>>>(W_xproj, W_dt, b_dt);
    k4_seg<<<dim3(BATCH, DINNER / 128, SEG), 128>>>(A_log, D_param);
    k4_combine<<<dim3(BATCH, DINNER / 128), 128>>>();
    k5_head<<<BATCH, 256>>>(W_out, W_outfc, b_outfc, W_mu, b_mu, W_sigma, b_sigma, out);
}

// round 8
// speedup vs baseline: 1.7737x; 1.2632x over previous
#include <cuda_runtime.h>
#include <math.h>
#include <stdint.h>

// Problem dims
#define BATCH 64
#define SEQLEN 256
#define DMODEL 256
#define DINNER 512
#define DSTATE 16
#define DTRANK 16
#define DCONV 4
#define DIMIN 256
#define DIMOUT 64
#define BL (BATCH * SEQLEN)      // 16384
#define SEG 8
#define LSEG (SEQLEN / SEG)      // 32

// Scratch (device globals: no cudaMalloc allowed)
__device__ float g_xin[BL * DINNER];
__device__ float g_z[BL * DINNER];
__device__ float g_xc[BL * DINNER];
__device__ float g_delta[BL * DINNER];
__device__ float g_Bm[BL * DSTATE];
__device__ float g_Cm[BL * DSTATE];
__device__ float g_ybar[BATCH * DINNER];
// segment scan partials
__device__ float g_segW[SEG * BATCH * DINNER * DSTATE];
__device__ float g_segP[SEG * BATCH * DINNER * DSTATE];
__device__ float g_segV[SEG * BATCH * DINNER * DSTATE];
__device__ float g_segc[SEG * BATCH * DINNER];

// ---------------------------------------------------------------------------
// K1: xz = input @ W_in^T via tf32 tensor-core mma (R4-proven, ~70us).
// M=16384, N=1024, K=256. Block 128x128x32, 8 warps, warp tile 64x32.
// ---------------------------------------------------------------------------
__device__ __forceinline__ uint32_t f2tf32(float x) {
    uint32_t u;
    asm("cvt.rna.tf32.f32 %0, %1;" : "=r"(u) : "f"(x));
    return u;
}

__global__ __launch_bounds__(256) void k1_gemm(const float* __restrict__ X,
                                               const float* __restrict__ W) {
    __shared__ uint32_t Xs[128][36];   // [m][k], pad 36 -> conflict-free frag loads
    __shared__ uint32_t Ws[128][36];   // [n][k]

    const int m0 = blockIdx.y * 128;
    const int n0 = blockIdx.x * 128;
    const int tid = threadIdx.x;
    const int wid = tid >> 5;
    const int lane = tid & 31;
    const int warp_m = wid & 1;
    const int warp_n = wid >> 1;
    const int g = lane >> 2;
    const int tig = lane & 3;

    float c[4][4][4];
#pragma unroll
    for (int ma = 0; ma < 4; ma++)
#pragma unroll
        for (int na = 0; na < 4; na++)
#pragma unroll
            for (int q = 0; q < 4; q++) c[ma][na][q] = 0.f;

    const int lrow = tid >> 1;
    const int lc4 = (tid & 1) * 16;

#pragma unroll 1
    for (int chunk = 0; chunk < 8; chunk++) {
        const int k0 = chunk * 32;
#pragma unroll
        for (int i = 0; i < 4; i++) {
            float4 v = *reinterpret_cast<const float4*>(&X[(size_t)(m0 + lrow) * 256 + k0 + lc4 + i * 4]);
            Xs[lrow][lc4 + i * 4 + 0] = f2tf32(v.x);
            Xs[lrow][lc4 + i * 4 + 1] = f2tf32(v.y);
            Xs[lrow][lc4 + i * 4 + 2] = f2tf32(v.z);
            Xs[lrow][lc4 + i * 4 + 3] = f2tf32(v.w);
            float4 w = *reinterpret_cast<const float4*>(&W[(size_t)(n0 + lrow) * 256 + k0 + lc4 + i * 4]);
            Ws[lrow][lc4 + i * 4 + 0] = f2tf32(w.x);
            Ws[lrow][lc4 + i * 4 + 1] = f2tf32(w.y);
            Ws[lrow][lc4 + i * 4 + 2] = f2tf32(w.z);
            Ws[lrow][lc4 + i * 4 + 3] = f2tf32(w.w);
        }
        __syncthreads();

#pragma unroll
        for (int ks = 0; ks < 4; ks++) {
            const int kk = ks * 8;
            uint32_t a[4][4];
#pragma unroll
            for (int ma = 0; ma < 4; ma++) {
                const int ar = warp_m * 64 + ma * 16 + g;
                a[ma][0] = Xs[ar][kk + tig];
                a[ma][1] = Xs[ar + 8][kk + tig];
                a[ma][2] = Xs[ar][kk + tig + 4];
                a[ma][3] = Xs[ar + 8][kk + tig + 4];
            }
            uint32_t bfr[4][2];
#pragma unroll
            for (int na = 0; na < 4; na++) {
                const int br = warp_n * 32 + na * 8 + g;
                bfr[na][0] = Ws[br][kk + tig];
                bfr[na][1] = Ws[br][kk + tig + 4];
            }
#pragma unroll
            for (int ma = 0; ma < 4; ma++)
#pragma unroll
                for (int na = 0; na < 4; na++) {
                    asm volatile(
                        "mma.sync.aligned.m16n8k8.row.col.f32.tf32.tf32.f32 "
                        "{%0,%1,%2,%3}, {%4,%5,%6,%7}, {%8,%9}, {%0,%1,%2,%3};"
                        : "+f"(c[ma][na][0]), "+f"(c[ma][na][1]),
                          "+f"(c[ma][na][2]), "+f"(c[ma][na][3])
                        : "r"(a[ma][0]), "r"(a[ma][1]), "r"(a[ma][2]), "r"(a[ma][3]),
                          "r"(bfr[na][0]), "r"(bfr[na][1]));
                }
        }
        __syncthreads();
    }

    float* dstbase = (n0 < DINNER) ? g_xin : g_z;
    const int nbase = (n0 < DINNER) ? n0 : (n0 - DINNER);
#pragma unroll
    for (int ma = 0; ma < 4; ma++) {
        const int m = m0 + warp_m * 64 + ma * 16 + g;
#pragma unroll
        for (int na = 0; na < 4; na++) {
            const int n = nbase + warp_n * 32 + na * 8 + tig * 2;
            *reinterpret_cast<float2*>(&dstbase[(size_t)m * DINNER + n]) =
                make_float2(c[ma][na][0], c[ma][na][1]);
            *reinterpret_cast<float2*>(&dstbase[(size_t)(m + 8) * DINNER + n]) =
                make_float2(c[ma][na][2], c[ma][na][3]);
        }
    }
}

// ---------------------------------------------------------------------------
// K2: causal depthwise conv (width 4) + bias + SiLU   (R2-proven)
// ---------------------------------------------------------------------------
__global__ __launch_bounds__(256) void k2_conv(const float* __restrict__ cw,
                                               const float* __restrict__ cb) {
    int idx = blockIdx.x * blockDim.x + threadIdx.x;
    if (idx >= BL * DINNER) return;
    int d = idx % DINNER;
    int l = (idx / DINNER) % SEQLEN;
    int b = idx / (DINNER * SEQLEN);

    float s = cb[d];
#pragma unroll
    for (int j = 0; j < DCONV; j++) {
        int li = l - (DCONV - 1) + j;
        if (li >= 0) s = fmaf(g_xin[(b * SEQLEN + li) * DINNER + d], cw[d * DCONV + j], s);
    }
    float sig = 1.f / (1.f + expf(-s));
    g_xc[idx] = s * sig;
}

// ---------------------------------------------------------------------------
// K3: x_dbl = xc @ W_xproj^T (48 out); split dt/B/C;
// delta = softplus(dt@W_dt^T + b_dt).  (R2-proven 8-row version)
// ---------------------------------------------------------------------------
#define K3ROWS 8
__global__ __launch_bounds__(512) void k3_proj(const float* __restrict__ Wx,
                                               const float* __restrict__ Wdt,
                                               const float* __restrict__ bdt) {
    const int bl0 = blockIdx.x * K3ROWS;
    __shared__ float sx[K3ROWS][DINNER];
    __shared__ float sdbl[K3ROWS][48];
    const int tid = threadIdx.x;

#pragma unroll
    for (int r = 0; r < K3ROWS; r++) sx[r][tid] = g_xc[(size_t)(bl0 + r) * DINNER + tid];
    __syncthreads();

    const int w = tid >> 5, lane = tid & 31;
    for (int o = w; o < 48; o += 16) {
        float s[K3ROWS];
#pragma unroll
        for (int r = 0; r < K3ROWS; r++) s[r] = 0.f;
        for (int k = lane; k < DINNER; k += 32) {
            float wv = Wx[o * DINNER + k];
#pragma unroll
            for (int r = 0; r < K3ROWS; r++) s[r] = fmaf(sx[r][k], wv, s[r]);
        }
#pragma unroll
        for (int off = 16; off; off >>= 1)
#pragma unroll
            for (int r = 0; r < K3ROWS; r++) s[r] += __shfl_down_sync(0xFFFFFFFFu, s[r], off);
        if (lane == 0) {
#pragma unroll
            for (int r = 0; r < K3ROWS; r++) sdbl[r][o] = s[r];
        }
    }
    __syncthreads();

    if (tid < K3ROWS * 16) {
        int r = tid >> 4, n = tid & 15;
        g_Bm[(size_t)(bl0 + r) * DSTATE + n] = sdbl[r][DTRANK + n];
    } else if (tid < 2 * K3ROWS * 16) {
        int t = tid - K3ROWS * 16;
        int r = t >> 4, n = t & 15;
        g_Cm[(size_t)(bl0 + r) * DSTATE + n] = sdbl[r][DTRANK + DSTATE + n];
    }

    float bv = bdt[tid];
    float wr[DTRANK];
#pragma unroll
    for (int i = 0; i < DTRANK; i++) wr[i] = Wdt[tid * DTRANK + i];
#pragma unroll
    for (int r = 0; r < K3ROWS; r++) {
        float acc = bv;
#pragma unroll
        for (int i = 0; i < DTRANK; i++) acc = fmaf(sdbl[r][i], wr[i], acc);
        float sp = fmaxf(acc, 0.f) + log1pf(expf(-fabsf(acc)));
        g_delta[(size_t)(bl0 + r) * DINNER + tid] = sp;
    }
}

// ---------------------------------------------------------------------------
// K4a: segmented selective scan (R3-proven). Grid (64, 4, SEG), 128 threads.
// ---------------------------------------------------------------------------
template <bool FAST>
__device__ __forceinline__ void seg_scan_body(
    int b, int d, int s, const float* __restrict__ A,
    float Dp, const float* __restrict__ sB, const float* __restrict__ sC)
{
    float P[DSTATE], V[DSTATE], Wc[DSTATE];
#pragma unroll
    for (int n = 0; n < DSTATE; n++) { P[n] = 1.f; V[n] = 0.f; Wc[n] = 0.f; }
    float c = 0.f;
    const float A0 = A[0];

    const int l0 = s * LSEG;
    const float* pdelta = g_delta + ((size_t)(b * SEQLEN + l0)) * DINNER + d;
    const float* pxc    = g_xc    + ((size_t)(b * SEQLEN + l0)) * DINNER + d;
    const float* pz     = g_z     + ((size_t)(b * SEQLEN + l0)) * DINNER + d;

    float dt  = pdelta[0];
    float xcv = pxc[0];
    float zv  = pz[0];

#pragma unroll 4
    for (int l = 0; l < LSEG; l++) {
        float dtn = 0.f, xcn = 0.f, zvn = 0.f;
        if (l + 1 < LSEG) {
            dtn = pdelta[(l + 1) * DINNER];
            xcn = pxc[(l + 1) * DINNER];
            zvn = pz[(l + 1) * DINNER];
        }
        float gate = __fdividef(zv, 1.f + __expf(-zv));
        float du = dt * xcv;
        float yl = 0.f;

        float dA[DSTATE];
        if (FAST) {
            float r  = __expf(dt * A0);
            float r2 = r * r;
            float r4 = r2 * r2;
            float r8 = r4 * r4;
            dA[0]  = r;          dA[1]  = r2;         dA[2]  = r2 * r;     dA[3]  = r4;
            dA[4]  = r4 * r;     dA[5]  = r4 * r2;    dA[6]  = r4 * dA[2]; dA[7]  = r8;
            dA[8]  = r8 * r;     dA[9]  = r8 * r2;    dA[10] = r8 * dA[2]; dA[11] = r8 * r4;
            dA[12] = r8 * dA[4]; dA[13] = r8 * dA[5]; dA[14] = r8 * dA[6]; dA[15] = r8 * r8;
        } else {
#pragma unroll
            for (int n = 0; n < DSTATE; n++) dA[n] = __expf(dt * A[n]);
        }

#pragma unroll
        for (int n = 0; n < DSTATE; n++) {
            float Bn = sB[l * DSTATE + n];
            float Cn = sC[l * DSTATE + n];
            P[n] *= dA[n];
            V[n] = fmaf(dA[n], V[n], du * Bn);
            yl = fmaf(V[n], Cn, yl);
            Wc[n] = fmaf(gate * Cn, P[n], Wc[n]);
        }
        c = fmaf(gate, fmaf(xcv, Dp, yl), c);
        dt = dtn; xcv = xcn; zv = zvn;
    }

    size_t base = (((size_t)s * BATCH + b) * DINNER + d) * DSTATE;
#pragma unroll
    for (int q = 0; q < DSTATE; q += 4) {
        *reinterpret_cast<float4*>(&g_segP[base + q]) = make_float4(P[q], P[q+1], P[q+2], P[q+3]);
        *reinterpret_cast<float4*>(&g_segV[base + q]) = make_float4(V[q], V[q+1], V[q+2], V[q+3]);
        *reinterpret_cast<float4*>(&g_segW[base + q]) = make_float4(Wc[q], Wc[q+1], Wc[q+2], Wc[q+3]);
    }
    g_segc[((size_t)s * BATCH + b) * DINNER + d] = c;
}

__global__ __launch_bounds__(128) void k4_seg(const float* __restrict__ A_log,
                                              const float* __restrict__ D_param) {
    const int b = blockIdx.x;
    const int d = blockIdx.y * 128 + threadIdx.x;
    const int s = blockIdx.z;

    __shared__ float sB[LSEG * DSTATE];
    __shared__ float sC[LSEG * DSTATE];
    {
        const float* gB = g_Bm + ((size_t)b * SEQLEN + s * LSEG) * DSTATE;
        const float* gC = g_Cm + ((size_t)b * SEQLEN + s * LSEG) * DSTATE;
        for (int i = threadIdx.x * 4; i < LSEG * DSTATE; i += 128 * 4) {
            *reinterpret_cast<float4*>(&sB[i]) = *reinterpret_cast<const float4*>(&gB[i]);
            *reinterpret_cast<float4*>(&sC[i]) = *reinterpret_cast<const float4*>(&gC[i]);
        }
    }
    __syncthreads();

    float A[DSTATE];
    bool fast = true;
#pragma unroll
    for (int n = 0; n < DSTATE; n++) {
        A[n] = -expf(A_log[d * DSTATE + n]);
        fast = fast && (fabsf(A[n] - (float)(n + 1) * A[0]) <= 1e-4f * fabsf(A[n]));
    }
    const float Dp = D_param[d];

    if (fast) seg_scan_body<true >(b, d, s, A, Dp, sB, sC);
    else      seg_scan_body<false>(b, d, s, A, Dp, sB, sC);
}

// K4b: combine segments. Grid (64,4), 128 threads.
__global__ __launch_bounds__(128) void k4_combine() {
    const int b = blockIdx.x;
    const int d = blockIdx.y * 128 + threadIdx.x;

    float h[DSTATE];
#pragma unroll
    for (int n = 0; n < DSTATE; n++) h[n] = 0.f;
    float ysum = 0.f;

#pragma unroll
    for (int s = 0; s < SEG; s++) {
        size_t base = (((size_t)s * BATCH + b) * DINNER + d) * DSTATE;
        float dot = g_segc[((size_t)s * BATCH + b) * DINNER + d];
#pragma unroll
        for (int q = 0; q < DSTATE; q += 4) {
            float4 Wv = *reinterpret_cast<const float4*>(&g_segW[base + q]);
            float4 Pv = *reinterpret_cast<const float4*>(&g_segP[base + q]);
            float4 Vv = *reinterpret_cast<const float4*>(&g_segV[base + q]);
            dot = fmaf(Wv.x, h[q+0], dot);
            dot = fmaf(Wv.y, h[q+1], dot);
            dot = fmaf(Wv.z, h[q+2], dot);
            dot = fmaf(Wv.w, h[q+3], dot);
            h[q+0] = fmaf(Pv.x, h[q+0], Vv.x);
            h[q+1] = fmaf(Pv.y, h[q+1], Vv.y);
            h[q+2] = fmaf(Pv.z, h[q+2], Vv.z);
            h[q+3] = fmaf(Pv.w, h[q+3], Vv.w);
        }
        ysum += dot;
    }
    g_ybar[(size_t)b * DINNER + d] = ysum * (1.f / (float)SEQLEN);
}

// ---------------------------------------------------------------------------
// K5: head, warp-cooperative coalesced dots (R6-proven).
// ---------------------------------------------------------------------------
__device__ __forceinline__ float warp_dot(const float* __restrict__ wrow,
                                          const float* __restrict__ svec,
                                          int K, int lane) {
    float s = 0.f;
    for (int k = lane * 4; k < K; k += 128) {
        float4 wv = *reinterpret_cast<const float4*>(&wrow[k]);
        s = fmaf(svec[k + 0], wv.x, s);
        s = fmaf(svec[k + 1], wv.y, s);
        s = fmaf(svec[k + 2], wv.z, s);
        s = fmaf(svec[k + 3], wv.w, s);
    }
#pragma unroll
    for (int off = 16; off; off >>= 1) s += __shfl_down_sync(0xFFFFFFFFu, s, off);
    return s;
}

__global__ __launch_bounds__(256) void k5_head(const float* __restrict__ W_out,
                                               const float* __restrict__ W_outfc,
                                               const float* __restrict__ b_outfc,
                                               const float* __restrict__ W_mu,
                                               const float* __restrict__ b_mu,
                                               const float* __restrict__ W_sigma,
                                               const float* __restrict__ b_sigma,
                                               float* __restrict__ out) {
    const int b = blockIdx.x;
    const int tid = threadIdx.x;
    const int w = tid >> 5, lane = tid & 31;
    __shared__ float sy[DINNER];
    __shared__ float se[DMODEL];
    __shared__ float sxv[DIMIN];

    sy[tid] = g_ybar[(size_t)b * DINNER + tid];
    sy[tid + 256] = g_ybar[(size_t)b * DINNER + tid + 256];
    __syncthreads();

#pragma unroll
    for (int oi = 0; oi < 32; oi++) {
        const int o = w + oi * 8;
        float s = warp_dot(&W_out[o * DINNER], sy, DINNER, lane);
        if (lane == 0) se[o] = s;
    }
    __syncthreads();

#pragma unroll
    for (int oi = 0; oi < 32; oi++) {
        const int o = w + oi * 8;
        float s = warp_dot(&W_outfc[o * DMODEL], se, DMODEL, lane);
        if (lane == 0) {
            s += b_outfc[o];
            float t = tanhf(s);
            float xv = (t > 0.f) ? t : expm1f(t);
            sxv[o] = xv;
            out[(size_t)b * DIMIN + o] = xv;
        }
    }
    __syncthreads();

    float* out_mu    = out + BATCH * DIMIN;
    float* out_sigma = out + BATCH * DIMIN + BATCH * DIMOUT;
#pragma unroll
    for (int oi = 0; oi < 16; oi++) {
        const int o = w + oi * 8;
        if (o < DIMOUT) {
            float s = warp_dot(&W_mu[o * DIMIN], sxv, DIMIN, lane);
            if (lane == 0) out_mu[(size_t)b * DIMOUT + o] = s + b_mu[o];
        } else {
            const int o2 = o - DIMOUT;
            float s = warp_dot(&W_sigma[o2 * DIMIN], sxv, DIMIN, lane);
            if (lane == 0) {
                s += b_sigma[o2];
                float el = (s > 0.f) ? s : expm1f(s);
                out_sigma[(size_t)b * DIMOUT + o2] = el + 1.f + 1e-14f;
            }
        }
    }
}

// ---------------------------------------------------------------------------
extern "C" void kernel_launch(void* const* d_in, const int* in_sizes, int n_in,
                              void* d_out, int out_size) {
    const float* input   = (const float*)d_in[0];
    const float* W_in    = (const float*)d_in[1];
    const float* conv_w  = (const float*)d_in[2];
    const float* conv_b  = (const float*)d_in[3];
    const float* W_xproj = (const float*)d_in[4];
    const float* W_dt    = (const float*)d_in[5];
    const float* b_dt    = (const float*)d_in[6];
    const float* A_log   = (const float*)d_in[7];
    const float* D_param = (const float*)d_in[8];
    const float* W_out   = (const float*)d_in[9];
    const float* W_outfc = (const float*)d_in[10];
    const float* b_outfc = (const float*)d_in[11];
    const float* W_mu    = (const float*)d_in[12];
    const float* b_mu    = (const float*)d_in[13];
    const float* W_sigma = (const float*)d_in[14];
    const float* b_sigma = (const float*)d_in[15];
    float* out = (float*)d_out;

    k1_gemm<<<dim3(1024 / 128, BL / 128), 256>>>(input, W_in);
    k2_conv<<<(BL * DINNER + 255) / 256, 256>>>(conv_w, conv_b);
    k3_proj<<<BL / K3ROWS, 512>>>(W_xproj, W_dt, b_dt);
    k4_seg<<<dim3(BATCH, DINNER / 128, SEG), 128>>>(A_log, D_param);
    k4_combine<<<dim3(BATCH, DINNER / 128), 128>>>();
    k5_head<<<BATCH, 256>>>(W_out, W_outfc, b_outfc, W_mu, b_mu, W_sigma, b_sigma, out);
}

// round 9
// speedup vs baseline: 1.8692x; 1.0538x over previous
#include <cuda_runtime.h>
#include <math.h>
#include <stdint.h>

// Problem dims
#define BATCH 64
#define SEQLEN 256
#define DMODEL 256
#define DINNER 512
#define DSTATE 16
#define DTRANK 16
#define DCONV 4
#define DIMIN 256
#define DIMOUT 64
#define BL (BATCH * SEQLEN)      // 16384
#define SEG 8
#define LSEG (SEQLEN / SEG)      // 32

// Scratch (device globals: no cudaMalloc allowed)
__device__ float g_xin[BL * DINNER];
__device__ float g_z[BL * DINNER];
__device__ float g_xc[BL * DINNER];
__device__ float g_delta[BL * DINNER];
__device__ float g_Bm[BL * DSTATE];
__device__ float g_Cm[BL * DSTATE];
__device__ float g_ybar[BATCH * DINNER];
// segment scan partials
__device__ float g_segW[SEG * BATCH * DINNER * DSTATE];
__device__ float g_segP[SEG * BATCH * DINNER * DSTATE];
__device__ float g_segV[SEG * BATCH * DINNER * DSTATE];
__device__ float g_segc[SEG * BATCH * DINNER];

// ---------------------------------------------------------------------------
// K1: xz = input @ W_in^T via tf32 tensor-core mma (R8-proven).
// ---------------------------------------------------------------------------
__device__ __forceinline__ uint32_t f2tf32(float x) {
    uint32_t u;
    asm("cvt.rna.tf32.f32 %0, %1;" : "=r"(u) : "f"(x));
    return u;
}

__global__ __launch_bounds__(256) void k1_gemm(const float* __restrict__ X,
                                               const float* __restrict__ W) {
    __shared__ uint32_t Xs[128][36];
    __shared__ uint32_t Ws[128][36];

    const int m0 = blockIdx.y * 128;
    const int n0 = blockIdx.x * 128;
    const int tid = threadIdx.x;
    const int wid = tid >> 5;
    const int lane = tid & 31;
    const int warp_m = wid & 1;
    const int warp_n = wid >> 1;
    const int g = lane >> 2;
    const int tig = lane & 3;

    float c[4][4][4];
#pragma unroll
    for (int ma = 0; ma < 4; ma++)
#pragma unroll
        for (int na = 0; na < 4; na++)
#pragma unroll
            for (int q = 0; q < 4; q++) c[ma][na][q] = 0.f;

    const int lrow = tid >> 1;
    const int lc4 = (tid & 1) * 16;

#pragma unroll 1
    for (int chunk = 0; chunk < 8; chunk++) {
        const int k0 = chunk * 32;
#pragma unroll
        for (int i = 0; i < 4; i++) {
            float4 v = *reinterpret_cast<const float4*>(&X[(size_t)(m0 + lrow) * 256 + k0 + lc4 + i * 4]);
            Xs[lrow][lc4 + i * 4 + 0] = f2tf32(v.x);
            Xs[lrow][lc4 + i * 4 + 1] = f2tf32(v.y);
            Xs[lrow][lc4 + i * 4 + 2] = f2tf32(v.z);
            Xs[lrow][lc4 + i * 4 + 3] = f2tf32(v.w);
            float4 w = *reinterpret_cast<const float4*>(&W[(size_t)(n0 + lrow) * 256 + k0 + lc4 + i * 4]);
            Ws[lrow][lc4 + i * 4 + 0] = f2tf32(w.x);
            Ws[lrow][lc4 + i * 4 + 1] = f2tf32(w.y);
            Ws[lrow][lc4 + i * 4 + 2] = f2tf32(w.z);
            Ws[lrow][lc4 + i * 4 + 3] = f2tf32(w.w);
        }
        __syncthreads();

#pragma unroll
        for (int ks = 0; ks < 4; ks++) {
            const int kk = ks * 8;
            uint32_t a[4][4];
#pragma unroll
            for (int ma = 0; ma < 4; ma++) {
                const int ar = warp_m * 64 + ma * 16 + g;
                a[ma][0] = Xs[ar][kk + tig];
                a[ma][1] = Xs[ar + 8][kk + tig];
                a[ma][2] = Xs[ar][kk + tig + 4];
                a[ma][3] = Xs[ar + 8][kk + tig + 4];
            }
            uint32_t bfr[4][2];
#pragma unroll
            for (int na = 0; na < 4; na++) {
                const int br = warp_n * 32 + na * 8 + g;
                bfr[na][0] = Ws[br][kk + tig];
                bfr[na][1] = Ws[br][kk + tig + 4];
            }
#pragma unroll
            for (int ma = 0; ma < 4; ma++)
#pragma unroll
                for (int na = 0; na < 4; na++) {
                    asm volatile(
                        "mma.sync.aligned.m16n8k8.row.col.f32.tf32.tf32.f32 "
                        "{%0,%1,%2,%3}, {%4,%5,%6,%7}, {%8,%9}, {%0,%1,%2,%3};"
                        : "+f"(c[ma][na][0]), "+f"(c[ma][na][1]),
                          "+f"(c[ma][na][2]), "+f"(c[ma][na][3])
                        : "r"(a[ma][0]), "r"(a[ma][1]), "r"(a[ma][2]), "r"(a[ma][3]),
                          "r"(bfr[na][0]), "r"(bfr[na][1]));
                }
        }
        __syncthreads();
    }

    float* dstbase = (n0 < DINNER) ? g_xin : g_z;
    const int nbase = (n0 < DINNER) ? n0 : (n0 - DINNER);
#pragma unroll
    for (int ma = 0; ma < 4; ma++) {
        const int m = m0 + warp_m * 64 + ma * 16 + g;
#pragma unroll
        for (int na = 0; na < 4; na++) {
            const int n = nbase + warp_n * 32 + na * 8 + tig * 2;
            *reinterpret_cast<float2*>(&dstbase[(size_t)m * DINNER + n]) =
                make_float2(c[ma][na][0], c[ma][na][1]);
            *reinterpret_cast<float2*>(&dstbase[(size_t)(m + 8) * DINNER + n]) =
                make_float2(c[ma][na][2], c[ma][na][3]);
        }
    }
}

// ---------------------------------------------------------------------------
// K3 (fused conv + 8-row proj): conv(width4,causal)+bias+SiLU in smem,
// write g_xc, then x_dbl = xc @ W_xproj^T; split dt/B/C;
// delta = softplus(dt@W_dt^T + b_dt). 512 threads, proven 8-row proj loop.
// ---------------------------------------------------------------------------
#define K3ROWS 8
__global__ __launch_bounds__(512) void k3_convproj(const float* __restrict__ cw,
                                                   const float* __restrict__ cb,
                                                   const float* __restrict__ Wx,
                                                   const float* __restrict__ Wdt,
                                                   const float* __restrict__ bdt) {
    const int bl0 = blockIdx.x * K3ROWS;
    const int l0 = bl0 & (SEQLEN - 1);          // blocks never cross batch
    __shared__ float sx[K3ROWS + 3][DINNER];    // rows bl0-3 .. bl0+7
    __shared__ float sdbl[K3ROWS][48];
    const int tid = threadIdx.x;

#pragma unroll
    for (int j = 0; j < K3ROWS + 3; j++) {
        int bl = bl0 - 3 + j;
        sx[j][tid] = (l0 + j >= 3) ? g_xin[(size_t)bl * DINNER + tid] : 0.f;
    }

    // conv + bias + SiLU in place (thread-private column, read-before-write)
    const float w0 = cw[tid * 4 + 0], w1 = cw[tid * 4 + 1];
    const float w2 = cw[tid * 4 + 2], w3 = cw[tid * 4 + 3];
    const float bias = cb[tid];
#pragma unroll
    for (int r = 0; r < K3ROWS; r++) {
        float sum = bias;
        sum = fmaf(sx[r + 0][tid], w0, sum);
        sum = fmaf(sx[r + 1][tid], w1, sum);
        sum = fmaf(sx[r + 2][tid], w2, sum);
        sum = fmaf(sx[r + 3][tid], w3, sum);
        float xc = sum / (1.f + expf(-sum));
        sx[r][tid] = xc;                        // xc row r now at slot r
        g_xc[(size_t)(bl0 + r) * DINNER + tid] = xc;
    }
    __syncthreads();

    const int w = tid >> 5, lane = tid & 31;
    for (int o = w; o < 48; o += 16) {
        float s[K3ROWS];
#pragma unroll
        for (int r = 0; r < K3ROWS; r++) s[r] = 0.f;
        for (int k = lane; k < DINNER; k += 32) {
            float wv = Wx[o * DINNER + k];
#pragma unroll
            for (int r = 0; r < K3ROWS; r++) s[r] = fmaf(sx[r][k], wv, s[r]);
        }
#pragma unroll
        for (int off = 16; off; off >>= 1)
#pragma unroll
            for (int r = 0; r < K3ROWS; r++) s[r] += __shfl_down_sync(0xFFFFFFFFu, s[r], off);
        if (lane == 0) {
#pragma unroll
            for (int r = 0; r < K3ROWS; r++) sdbl[r][o] = s[r];
        }
    }
    __syncthreads();

    if (tid < K3ROWS * 16) {
        int r = tid >> 4, n = tid & 15;
        g_Bm[(size_t)(bl0 + r) * DSTATE + n] = sdbl[r][DTRANK + n];
    } else if (tid < 2 * K3ROWS * 16) {
        int t = tid - K3ROWS * 16;
        int r = t >> 4, n = t & 15;
        g_Cm[(size_t)(bl0 + r) * DSTATE + n] = sdbl[r][DTRANK + DSTATE + n];
    }

    float bv = bdt[tid];
    float wr[DTRANK];
#pragma unroll
    for (int i = 0; i < DTRANK; i++) wr[i] = Wdt[tid * DTRANK + i];
#pragma unroll
    for (int r = 0; r < K3ROWS; r++) {
        float acc = bv;
#pragma unroll
        for (int i = 0; i < DTRANK; i++) acc = fmaf(sdbl[r][i], wr[i], acc);
        float sp = fmaxf(acc, 0.f) + log1pf(expf(-fabsf(acc)));
        g_delta[(size_t)(bl0 + r) * DINNER + tid] = sp;
    }
}

// ---------------------------------------------------------------------------
// K4a: segmented selective scan. Grid (64, 4, SEG), 128 threads.
// FAST path: P[n] = Rcum^(n+1) via per-step power tree (fewer live regs).
// ---------------------------------------------------------------------------
__device__ __forceinline__ void pow_tree(float r, float* out) {
    float r2 = r * r;
    float r4 = r2 * r2;
    float r8 = r4 * r4;
    out[0]  = r;          out[1]  = r2;         out[2]  = r2 * r;      out[3]  = r4;
    out[4]  = r4 * r;     out[5]  = r4 * r2;    out[6]  = r4 * out[2]; out[7]  = r8;
    out[8]  = r8 * r;     out[9]  = r8 * r2;    out[10] = r8 * out[2]; out[11] = r8 * r4;
    out[12] = r8 * out[4]; out[13] = r8 * out[5]; out[14] = r8 * out[6]; out[15] = r8 * r8;
}

template <bool FAST>
__device__ __forceinline__ void seg_scan_body(
    int b, int d, int s, const float* __restrict__ A,
    float Dp, const float* __restrict__ sB, const float* __restrict__ sC)
{
    float V[DSTATE], Wc[DSTATE];
#pragma unroll
    for (int n = 0; n < DSTATE; n++) { V[n] = 0.f; Wc[n] = 0.f; }
    float Pfull[DSTATE];               // used only in !FAST
    if (!FAST) {
#pragma unroll
        for (int n = 0; n < DSTATE; n++) Pfull[n] = 1.f;
    }
    float Rcum = 1.f;                  // FAST: prod of r; P[n] = Rcum^(n+1)
    float c = 0.f;
    const float A0 = A[0];

    const int l0 = s * LSEG;
    const float* pdelta = g_delta + ((size_t)(b * SEQLEN + l0)) * DINNER + d;
    const float* pxc    = g_xc    + ((size_t)(b * SEQLEN + l0)) * DINNER + d;
    const float* pz     = g_z     + ((size_t)(b * SEQLEN + l0)) * DINNER + d;

    float dt  = pdelta[0];
    float xcv = pxc[0];
    float zv  = pz[0];

#pragma unroll 4
    for (int l = 0; l < LSEG; l++) {
        float dtn = 0.f, xcn = 0.f, zvn = 0.f;
        if (l + 1 < LSEG) {
            dtn = pdelta[(l + 1) * DINNER];
            xcn = pxc[(l + 1) * DINNER];
            zvn = pz[(l + 1) * DINNER];
        }
        float gate = __fdividef(zv, 1.f + __expf(-zv));
        float du = dt * xcv;
        float yl = 0.f;

        float dA[DSTATE];
        float Pw[DSTATE];
        if (FAST) {
            float r = __expf(dt * A0);
            pow_tree(r, dA);
            Rcum *= r;
            pow_tree(Rcum, Pw);        // prefix decay products
        } else {
#pragma unroll
            for (int n = 0; n < DSTATE; n++) {
                dA[n] = __expf(dt * A[n]);
                Pfull[n] *= dA[n];
                Pw[n] = Pfull[n];
            }
        }

#pragma unroll
        for (int n = 0; n < DSTATE; n++) {
            float Bn = sB[l * DSTATE + n];
            float Cn = sC[l * DSTATE + n];
            V[n] = fmaf(dA[n], V[n], du * Bn);
            yl = fmaf(V[n], Cn, yl);
            Wc[n] = fmaf(gate * Cn, Pw[n], Wc[n]);
        }
        c = fmaf(gate, fmaf(xcv, Dp, yl), c);
        dt = dtn; xcv = xcn; zv = zvn;
    }

    float Pout[DSTATE];
    if (FAST) pow_tree(Rcum, Pout);
    else {
#pragma unroll
        for (int n = 0; n < DSTATE; n++) Pout[n] = Pfull[n];
    }

    size_t base = (((size_t)s * BATCH + b) * DINNER + d) * DSTATE;
#pragma unroll
    for (int q = 0; q < DSTATE; q += 4) {
        *reinterpret_cast<float4*>(&g_segP[base + q]) = make_float4(Pout[q], Pout[q+1], Pout[q+2], Pout[q+3]);
        *reinterpret_cast<float4*>(&g_segV[base + q]) = make_float4(V[q], V[q+1], V[q+2], V[q+3]);
        *reinterpret_cast<float4*>(&g_segW[base + q]) = make_float4(Wc[q], Wc[q+1], Wc[q+2], Wc[q+3]);
    }
    g_segc[((size_t)s * BATCH + b) * DINNER + d] = c;
}

__global__ __launch_bounds__(128) void k4_seg(const float* __restrict__ A_log,
                                              const float* __restrict__ D_param) {
    const int b = blockIdx.x;
    const int d = blockIdx.y * 128 + threadIdx.x;
    const int s = blockIdx.z;

    __shared__ float sB[LSEG * DSTATE];
    __shared__ float sC[LSEG * DSTATE];
    {
        const float* gB = g_Bm + ((size_t)b * SEQLEN + s * LSEG) * DSTATE;
        const float* gC = g_Cm + ((size_t)b * SEQLEN + s * LSEG) * DSTATE;
        for (int i = threadIdx.x * 4; i < LSEG * DSTATE; i += 128 * 4) {
            *reinterpret_cast<float4*>(&sB[i]) = *reinterpret_cast<const float4*>(&gB[i]);
            *reinterpret_cast<float4*>(&sC[i]) = *reinterpret_cast<const float4*>(&gC[i]);
        }
    }
    __syncthreads();

    float A[DSTATE];
    bool fast = true;
#pragma unroll
    for (int n = 0; n < DSTATE; n++) {
        A[n] = -expf(A_log[d * DSTATE + n]);
        fast = fast && (fabsf(A[n] - (float)(n + 1) * A[0]) <= 1e-4f * fabsf(A[n]));
    }
    const float Dp = D_param[d];

    if (fast) seg_scan_body<true >(b, d, s, A, Dp, sB, sC);
    else      seg_scan_body<false>(b, d, s, A, Dp, sB, sC);
}

// K4b: combine segments. Grid (64,4), 128 threads.
__global__ __launch_bounds__(128) void k4_combine() {
    const int b = blockIdx.x;
    const int d = blockIdx.y * 128 + threadIdx.x;

    float h[DSTATE];
#pragma unroll
    for (int n = 0; n < DSTATE; n++) h[n] = 0.f;
    float ysum = 0.f;

#pragma unroll
    for (int s = 0; s < SEG; s++) {
        size_t base = (((size_t)s * BATCH + b) * DINNER + d) * DSTATE;
        float dot = g_segc[((size_t)s * BATCH + b) * DINNER + d];
#pragma unroll
        for (int q = 0; q < DSTATE; q += 4) {
            float4 Wv = *reinterpret_cast<const float4*>(&g_segW[base + q]);
            float4 Pv = *reinterpret_cast<const float4*>(&g_segP[base + q]);
            float4 Vv = *reinterpret_cast<const float4*>(&g_segV[base + q]);
            dot = fmaf(Wv.x, h[q+0], dot);
            dot = fmaf(Wv.y, h[q+1], dot);
            dot = fmaf(Wv.z, h[q+2], dot);
            dot = fmaf(Wv.w, h[q+3], dot);
            h[q+0] = fmaf(Pv.x, h[q+0], Vv.x);
            h[q+1] = fmaf(Pv.y, h[q+1], Vv.y);
            h[q+2] = fmaf(Pv.z, h[q+2], Vv.z);
            h[q+3] = fmaf(Pv.w, h[q+3], Vv.w);
        }
        ysum += dot;
    }
    g_ybar[(size_t)b * DINNER + d] = ysum * (1.f / (float)SEQLEN);
}

// ---------------------------------------------------------------------------
// K5: head, warp-cooperative coalesced dots (R6-proven).
// ---------------------------------------------------------------------------
__device__ __forceinline__ float warp_dot(const float* __restrict__ wrow,
                                          const float* __restrict__ svec,
                                          int K, int lane) {
    float s = 0.f;
    for (int k = lane * 4; k < K; k += 128) {
        float4 wv = *reinterpret_cast<const float4*>(&wrow[k]);
        s = fmaf(svec[k + 0], wv.x, s);
        s = fmaf(svec[k + 1], wv.y, s);
        s = fmaf(svec[k + 2], wv.z, s);
        s = fmaf(svec[k + 3], wv.w, s);
    }
#pragma unroll
    for (int off = 16; off; off >>= 1) s += __shfl_down_sync(0xFFFFFFFFu, s, off);
    return s;
}

__global__ __launch_bounds__(256) void k5_head(const float* __restrict__ W_out,
                                               const float* __restrict__ W_outfc,
                                               const float* __restrict__ b_outfc,
                                               const float* __restrict__ W_mu,
                                               const float* __restrict__ b_mu,
                                               const float* __restrict__ W_sigma,
                                               const float* __restrict__ b_sigma,
                                               float* __restrict__ out) {
    const int b = blockIdx.x;
    const int tid = threadIdx.x;
    const int w = tid >> 5, lane = tid & 31;
    __shared__ float sy[DINNER];
    __shared__ float se[DMODEL];
    __shared__ float sxv[DIMIN];

    sy[tid] = g_ybar[(size_t)b * DINNER + tid];
    sy[tid + 256] = g_ybar[(size_t)b * DINNER + tid + 256];
    __syncthreads();

#pragma unroll
    for (int oi = 0; oi < 32; oi++) {
        const int o = w + oi * 8;
        float s = warp_dot(&W_out[o * DINNER], sy, DINNER, lane);
        if (lane == 0) se[o] = s;
    }
    __syncthreads();

#pragma unroll
    for (int oi = 0; oi < 32; oi++) {
        const int o = w + oi * 8;
        float s = warp_dot(&W_outfc[o * DMODEL], se, DMODEL, lane);
        if (lane == 0) {
            s += b_outfc[o];
            float t = tanhf(s);
            float xv = (t > 0.f) ? t : expm1f(t);
            sxv[o] = xv;
            out[(size_t)b * DIMIN + o] = xv;
        }
    }
    __syncthreads();

    float* out_mu    = out + BATCH * DIMIN;
    float* out_sigma = out + BATCH * DIMIN + BATCH * DIMOUT;
#pragma unroll
    for (int oi = 0; oi < 16; oi++) {
        const int o = w + oi * 8;
        if (o < DIMOUT) {
            float s = warp_dot(&W_mu[o * DIMIN], sxv, DIMIN, lane);
            if (lane == 0) out_mu[(size_t)b * DIMOUT + o] = s + b_mu[o];
        } else {
            const int o2 = o - DIMOUT;
            float s = warp_dot(&W_sigma[o2 * DIMIN], sxv, DIMIN, lane);
            if (lane == 0) {
                s += b_sigma[o2];
                float el = (s > 0.f) ? s : expm1f(s);
                out_sigma[(size_t)b * DIMOUT + o2] = el + 1.f + 1e-14f;
            }
        }
    }
}

// ---------------------------------------------------------------------------
extern "C" void kernel_launch(void* const* d_in, const int* in_sizes, int n_in,
                              void* d_out, int out_size) {
    const float* input   = (const float*)d_in[0];
    const float* W_in    = (const float*)d_in[1];
    const float* conv_w  = (const float*)d_in[2];
    const float* conv_b  = (const float*)d_in[3];
    const float* W_xproj = (const float*)d_in[4];
    const float* W_dt    = (const float*)d_in[5];
    const float* b_dt    = (const float*)d_in[6];
    const float* A_log   = (const float*)d_in[7];
    const float* D_param = (const float*)d_in[8];
    const float* W_out   = (const float*)d_in[9];
    const float* W_outfc = (const float*)d_in[10];
    const float* b_outfc = (const float*)d_in[11];
    const float* W_mu    = (const float*)d_in[12];
    const float* b_mu    = (const float*)d_in[13];
    const float* W_sigma = (const float*)d_in[14];
    const float* b_sigma = (const float*)d_in[15];
    float* out = (float*)d_out;

    k1_gemm<<<dim3(1024 / 128, BL / 128), 256>>>(input, W_in);
    k3_convproj<<<BL / K3ROWS, 512>>>(conv_w, conv_b, W_xproj, W_dt, b_dt);
    k4_seg<<<dim3(BATCH, DINNER / 128, SEG), 128>>>(A_log, D_param);
    k4_combine<<<dim3(BATCH, DINNER / 128), 128>>>();
    k5_head<<<BATCH, 256>>>(W_out, W_outfc, b_outfc, W_mu, b_mu, W_sigma, b_sigma, out);
}